// round 12
// baseline (speedup 1.0000x reference)
#include <cuda_runtime.h>
#include <cuda_fp16.h>
#include <cstdint>

// Problem constants (fixed by reference)
#define DMODEL 1024
#define HEADS  16
#define DH     64
#define BATCH  4
#define SEQ    4096
#define ROWS   (BATCH * SEQ)   // 16384
#define KSPLIT 16
#define EPSV   1e-6f

// GEMM tiling (HMMA mma.sync; tcgen05 unavailable on compute_103 virtual arch)
#define BM 128
#define BN 256
#define NCH (DMODEL / 64)       // 16 chunks of 64 fp16 per 1024-row
#define GTHREADS 512
#define STAGES 3

// Blocked-swizzled fp16 layout: 16KB block per (row-tile of 128, 64-col chunk).
#define BLK_BYTES 16384

#define A_PL 0
#define B_PL 16384
#define STAGE 49152                          // A 16KB + B 32KB
#define SMEM_BYTES (1024 + STAGES * STAGE)   // 148480

#define KV_STAGE 32768                        // K 16KB + V 16KB
#define KV_SMEM  (1024 + 2 * KV_STAGE)        // 66560
#define AT_STAGE 24576                        // Q 16KB + kvT 8KB
#define AT_SMEM  (1024 + 2 * AT_STAGE)        // 50176

#define ASTRIDE ((size_t)ROWS * DMODEL)

// ---------------- scratch (device globals; no allocation allowed) ------------
__device__ __half g_Xb[3 * ROWS * DMODEL];          // blocked q/k/v inputs
__device__ __half g_Ab[ROWS * DMODEL];              // S (blocked)
__device__ __half g_Wb[4 * DMODEL * DMODEL];        // blocked wq,wk,wv,wo
__device__ __half g_Qb[ROWS * DMODEL];              // Q fp16 blocked
__device__ __half g_Kb[ROWS * DMODEL];              // K fp16 blocked
__device__ __half g_Vb[ROWS * DMODEL];              // V fp16 blocked
__device__ float g_kvp[BATCH * HEADS * KSPLIT * DH * DH];
__device__ float g_zp [BATCH * HEADS * KSPLIT * DH];
__device__ __half g_kvT[BATCH * HEADS * DH * DH];   // kv^T fp16 swizzled [e][d]
__device__ float g_z  [BATCH * HEADS * DH];

// =============================== helpers ====================================
__device__ __forceinline__ uint32_t smem_u32(const void* p) {
    uint32_t a;
    asm("{ .reg .u64 t; cvta.to.shared.u64 t, %1; cvt.u32.u64 %0, t; }"
        : "=r"(a) : "l"(p));
    return a;
}
__device__ __forceinline__ void ldsm4(uint32_t& r0, uint32_t& r1, uint32_t& r2,
                                      uint32_t& r3, uint32_t addr) {
    asm volatile("ldmatrix.sync.aligned.m8n8.x4.shared.b16 {%0,%1,%2,%3}, [%4];"
                 : "=r"(r0), "=r"(r1), "=r"(r2), "=r"(r3) : "r"(addr));
}
__device__ __forceinline__ void ldsm4t(uint32_t& r0, uint32_t& r1, uint32_t& r2,
                                       uint32_t& r3, uint32_t addr) {
    asm volatile("ldmatrix.sync.aligned.m8n8.x4.trans.shared.b16 {%0,%1,%2,%3}, [%4];"
                 : "=r"(r0), "=r"(r1), "=r"(r2), "=r"(r3) : "r"(addr));
}
__device__ __forceinline__ void mma_fp16(float* c, const uint32_t* a, const uint32_t* b) {
    asm volatile(
        "mma.sync.aligned.m16n8k16.row.col.f32.f16.f16.f32 "
        "{%0,%1,%2,%3}, {%4,%5,%6,%7}, {%8,%9}, {%0,%1,%2,%3};"
        : "+f"(c[0]), "+f"(c[1]), "+f"(c[2]), "+f"(c[3])
        : "r"(a[0]), "r"(a[1]), "r"(a[2]), "r"(a[3]), "r"(b[0]), "r"(b[1]));
}
__device__ __forceinline__ void mbar_init(uint32_t addr, uint32_t cnt) {
    asm volatile("mbarrier.init.shared.b64 [%0], %1;" :: "r"(addr), "r"(cnt) : "memory");
}
__device__ __forceinline__ void mbar_expect_tx(uint32_t addr, uint32_t bytes) {
    asm volatile("mbarrier.arrive.expect_tx.shared.b64 _, [%0], %1;"
                 :: "r"(addr), "r"(bytes) : "memory");
}
__device__ __forceinline__ void mbar_wait(uint32_t addr, uint32_t parity) {
    asm volatile(
        "{\n\t.reg .pred P;\n"
        "W%=:\n\t"
        "mbarrier.try_wait.parity.acquire.cta.shared::cta.b64 P, [%0], %1, 0x989680;\n\t"
        "@!P bra W%=;\n\t"
        "}"
        :: "r"(addr), "r"(parity) : "memory");
}
__device__ __forceinline__ void bulk_cp(uint32_t sdst, const void* gsrc,
                                        uint32_t bytes, uint32_t mbar) {
    asm volatile(
        "cp.async.bulk.shared::cta.global.mbarrier::complete_tx::bytes [%0], [%1], %2, [%3];"
        :: "r"(sdst), "l"(gsrc), "r"(bytes), "r"(mbar) : "memory");
}
__device__ __forceinline__ uint2 cvt_f16x4(float4 v) {
    __half2 p01 = __floats2half2_rn(v.x, v.y);
    __half2 p23 = __floats2half2_rn(v.z, v.w);
    return make_uint2(*(uint32_t*)&p01, *(uint32_t*)&p23);
}
__device__ __forceinline__ float h2sum(uint32_t r) {
    float2 f = __half22float2(*(__half2*)&r);
    return f.x + f.y;
}

// =============================================================================
// fp32 [rows][1024] -> blocked-swizzled fp16; up to 4 tensors per launch (z).
// Each thread handles 8 floats -> ONE 16B store (16B = swizzle atom, aligned).
// =============================================================================
__global__ __launch_bounds__(256)
void cvt_swz_multi(const float* __restrict__ s0, const float* __restrict__ s1,
                   const float* __restrict__ s2, const float* __restrict__ s3,
                   __half* __restrict__ dst, size_t dstride, int n8) {
    const float* src = (blockIdx.z == 0) ? s0 : (blockIdx.z == 1) ? s1
                     : (blockIdx.z == 2) ? s2 : s3;
    __half* d = dst + (size_t)blockIdx.z * dstride;
    for (int i = blockIdx.x * 256 + threadIdx.x; i < n8; i += gridDim.x * 256) {
        const int grow = i >> 7;
        const int gcol = (i & 127) * 8;
        const int blk  = grow >> 7;
        const int r    = grow & 127;
        const int c    = gcol >> 6;
        const uint32_t colb = (uint32_t)((gcol & 63) * 2);
        const size_t off = ((size_t)(blk * NCH + c) << 14)
                         + (uint32_t)(r * 128) + (colb ^ ((uint32_t)(r & 7) << 4));
        float4 va = ((const float4*)src)[2 * i];
        float4 vb = ((const float4*)src)[2 * i + 1];
        uint2 pa = cvt_f16x4(va);
        uint2 pb = cvt_f16x4(vb);
        *(uint4*)((char*)d + off) = make_uint4(pa.x, pa.y, pb.x, pb.y);
    }
}

// =============================================================================
// Merged QKV projection GEMM (NT), CTA tile 128x256, 512 threads (4m x 4n warps).
// grid.z selects {input, weight, bias, out, phi}. fp16 blocked in/out.
// =============================================================================
__global__ __launch_bounds__(GTHREADS, 1)
void gemm_qkv(const __half* __restrict__ Xb, const __half* __restrict__ Wb,
              const float* __restrict__ bq, const float* __restrict__ bk,
              const float* __restrict__ bv,
              __half* __restrict__ Qb, __half* __restrict__ Kb,
              __half* __restrict__ Vb) {
    extern __shared__ char sm[];
    const uint32_t sbase = smem_u32(sm);
    const int tid = threadIdx.x;
    const int lane = tid & 31;
    const int wid = tid >> 5;
    const int wm = wid & 3;          // 4 m-groups of 32 rows
    const int wn = wid >> 2;         // 4 n-groups of 64 cols
    const int bm = blockIdx.y;
    const int bn = blockIdx.x;
    const int zi = blockIdx.z;

    const __half* Ab = Xb + (size_t)zi * ASTRIDE;
    const __half* Bb = Wb + (size_t)zi * (DMODEL * DMODEL);
    const float* bias = (zi == 0) ? bq : (zi == 1) ? bk : bv;
    __half* Yh = (zi == 0) ? Qb : (zi == 1) ? Kb : Vb;
    const bool phi = (zi != 2);

    if (tid == 0) {
        #pragma unroll
        for (int s = 0; s < STAGES; s++) mbar_init(sbase + s * 8, 1);
    }
    __syncthreads();

    const char* gAb = (const char*)Ab + ((size_t)(bm * NCH) << 14);
    const char* gB0 = (const char*)Bb + ((size_t)((bn * 2) * NCH) << 14);
    const char* gB1 = (const char*)Bb + ((size_t)((bn * 2 + 1) * NCH) << 14);

    int row_a[2];
    row_a[0] = wm * 32 + (lane & 15);
    row_a[1] = row_a[0] + 16;
    const uint32_t a_colb = (uint32_t)((lane >> 4) << 4);
    uint32_t a_base[2], a_mask[2];
    #pragma unroll
    for (int mt = 0; mt < 2; mt++) {
        a_base[mt] = (uint32_t)(row_a[mt] * 128);
        a_mask[mt] = (uint32_t)((row_a[mt] & 7) << 4);
    }
    int nrow[4];
    #pragma unroll
    for (int ntp = 0; ntp < 4; ntp++)
        nrow[ntp] = wn * 64 + ntp * 16 + (lane & 7) + ((lane >> 4) << 3);
    const uint32_t b_colb = (lane & 8) ? 16u : 0u;
    uint32_t b_base[4], b_mask[4];
    #pragma unroll
    for (int ntp = 0; ntp < 4; ntp++) {
        b_base[ntp] = (uint32_t)((nrow[ntp] >> 7) * 16384 + (nrow[ntp] & 127) * 128);
        b_mask[ntp] = (uint32_t)((nrow[ntp] & 7) << 4);
    }

    float acc[2][8][4];
    #pragma unroll
    for (int mt = 0; mt < 2; mt++)
        #pragma unroll
        for (int nt = 0; nt < 8; nt++)
            #pragma unroll
            for (int i = 0; i < 4; i++) acc[mt][nt][i] = 0.f;

    auto issue = [&](int c) {
        const int s = c % STAGES;
        const uint32_t mb = sbase + s * 8;
        const uint32_t st = sbase + 1024 + s * STAGE;
        mbar_expect_tx(mb, 3 * BLK_BYTES);
        bulk_cp(st + A_PL,             gAb + ((size_t)c << 14), BLK_BYTES, mb);
        bulk_cp(st + B_PL,             gB0 + ((size_t)c << 14), BLK_BYTES, mb);
        bulk_cp(st + B_PL + BLK_BYTES, gB1 + ((size_t)c << 14), BLK_BYTES, mb);
    };

    if (tid == 0) { issue(0); issue(1); }

    for (int c = 0; c < NCH; c++) {
        mbar_wait(sbase + (c % STAGES) * 8, (c / STAGES) & 1);
        if (tid == 0 && c + 2 < NCH) issue(c + 2);

        const uint32_t stg = sbase + 1024 + (uint32_t)((c % STAGES) * STAGE);
        #pragma unroll
        for (int ks = 0; ks < 4; ks++) {
            const uint32_t kb = (uint32_t)(ks * 32);
            uint32_t Ar[2][4];
            #pragma unroll
            for (int mt = 0; mt < 2; mt++) {
                uint32_t off = a_base[mt] + ((kb + a_colb) ^ a_mask[mt]);
                ldsm4(Ar[mt][0], Ar[mt][1], Ar[mt][2], Ar[mt][3], stg + A_PL + off);
            }
            uint32_t Br[8][2];
            #pragma unroll
            for (int ntp = 0; ntp < 4; ntp++) {
                uint32_t off = b_base[ntp] + ((kb + b_colb) ^ b_mask[ntp]);
                ldsm4(Br[2 * ntp][0], Br[2 * ntp][1], Br[2 * ntp + 1][0], Br[2 * ntp + 1][1],
                      stg + B_PL + off);
            }
            #pragma unroll
            for (int mt = 0; mt < 2; mt++)
                #pragma unroll
                for (int nt = 0; nt < 8; nt++)
                    mma_fp16(acc[mt][nt], Ar[mt], Br[nt]);
        }
        __syncthreads();
    }

    // ---- epilogue: bias (+ phi), store fp16 blocked ----
    const int lr = lane >> 2;
    const int lc = lane & 3;
    #pragma unroll
    for (int mt = 0; mt < 2; mt++) {
        const int r0l = wm * 32 + mt * 16 + lr;
        #pragma unroll
        for (int nt = 0; nt < 8; nt++) {
            const int gc = bn * BN + wn * 64 + nt * 8 + lc * 2;
            const float b0 = __ldg(&bias[gc]);
            const float b1 = __ldg(&bias[gc + 1]);
            float o00 = acc[mt][nt][0] + b0;
            float o01 = acc[mt][nt][1] + b1;
            float o10 = acc[mt][nt][2] + b0;
            float o11 = acc[mt][nt][3] + b1;
            if (phi) {
                o00 = (o00 > 0.f) ? (o00 + 1.f) : __expf(o00);
                o01 = (o01 > 0.f) ? (o01 + 1.f) : __expf(o01);
                o10 = (o10 > 0.f) ? (o10 + 1.f) : __expf(o10);
                o11 = (o11 > 0.f) ? (o11 + 1.f) : __expf(o11);
            }
            const int cch = gc >> 6;
            const uint32_t colb = (uint32_t)((gc & 63) * 2);
            const size_t blkb = ((size_t)(bm * NCH + cch)) << 14;
            __half2 p0 = __floats2half2_rn(o00, o01);
            __half2 p1 = __floats2half2_rn(o10, o11);
            const uint32_t ra = (uint32_t)r0l, rb = (uint32_t)(r0l + 8);
            *(uint32_t*)((char*)Yh + blkb + ra * 128 + (colb ^ ((ra & 7) << 4))) =
                *(uint32_t*)&p0;
            *(uint32_t*)((char*)Yh + blkb + rb * 128 + (colb ^ ((rb & 7) << 4))) =
                *(uint32_t*)&p1;
        }
    }
}

// =============================================================================
// Output projection GEMM (fp32 row-major out), 128x256 tile, 512 threads.
// =============================================================================
__global__ __launch_bounds__(GTHREADS, 1)
void gemm_out(const __half* __restrict__ Ab, const __half* __restrict__ Bb,
              const float* __restrict__ bias, float* __restrict__ Y) {
    extern __shared__ char sm[];
    const uint32_t sbase = smem_u32(sm);
    const int tid = threadIdx.x;
    const int lane = tid & 31;
    const int wid = tid >> 5;
    const int wm = wid & 3;
    const int wn = wid >> 2;
    const int bm = blockIdx.y;
    const int bn = blockIdx.x;

    if (tid == 0) {
        #pragma unroll
        for (int s = 0; s < STAGES; s++) mbar_init(sbase + s * 8, 1);
    }
    __syncthreads();

    const char* gAb = (const char*)Ab + ((size_t)(bm * NCH) << 14);
    const char* gB0 = (const char*)Bb + ((size_t)((bn * 2) * NCH) << 14);
    const char* gB1 = (const char*)Bb + ((size_t)((bn * 2 + 1) * NCH) << 14);

    int row_a[2];
    row_a[0] = wm * 32 + (lane & 15);
    row_a[1] = row_a[0] + 16;
    const uint32_t a_colb = (uint32_t)((lane >> 4) << 4);
    uint32_t a_base[2], a_mask[2];
    #pragma unroll
    for (int mt = 0; mt < 2; mt++) {
        a_base[mt] = (uint32_t)(row_a[mt] * 128);
        a_mask[mt] = (uint32_t)((row_a[mt] & 7) << 4);
    }
    int nrow[4];
    #pragma unroll
    for (int ntp = 0; ntp < 4; ntp++)
        nrow[ntp] = wn * 64 + ntp * 16 + (lane & 7) + ((lane >> 4) << 3);
    const uint32_t b_colb = (lane & 8) ? 16u : 0u;
    uint32_t b_base[4], b_mask[4];
    #pragma unroll
    for (int ntp = 0; ntp < 4; ntp++) {
        b_base[ntp] = (uint32_t)((nrow[ntp] >> 7) * 16384 + (nrow[ntp] & 127) * 128);
        b_mask[ntp] = (uint32_t)((nrow[ntp] & 7) << 4);
    }

    float acc[2][8][4];
    #pragma unroll
    for (int mt = 0; mt < 2; mt++)
        #pragma unroll
        for (int nt = 0; nt < 8; nt++)
            #pragma unroll
            for (int i = 0; i < 4; i++) acc[mt][nt][i] = 0.f;

    auto issue = [&](int c) {
        const int s = c % STAGES;
        const uint32_t mb = sbase + s * 8;
        const uint32_t st = sbase + 1024 + s * STAGE;
        mbar_expect_tx(mb, 3 * BLK_BYTES);
        bulk_cp(st + A_PL,             gAb + ((size_t)c << 14), BLK_BYTES, mb);
        bulk_cp(st + B_PL,             gB0 + ((size_t)c << 14), BLK_BYTES, mb);
        bulk_cp(st + B_PL + BLK_BYTES, gB1 + ((size_t)c << 14), BLK_BYTES, mb);
    };

    if (tid == 0) { issue(0); issue(1); }

    for (int c = 0; c < NCH; c++) {
        mbar_wait(sbase + (c % STAGES) * 8, (c / STAGES) & 1);
        if (tid == 0 && c + 2 < NCH) issue(c + 2);

        const uint32_t stg = sbase + 1024 + (uint32_t)((c % STAGES) * STAGE);
        #pragma unroll
        for (int ks = 0; ks < 4; ks++) {
            const uint32_t kb = (uint32_t)(ks * 32);
            uint32_t Ar[2][4];
            #pragma unroll
            for (int mt = 0; mt < 2; mt++) {
                uint32_t off = a_base[mt] + ((kb + a_colb) ^ a_mask[mt]);
                ldsm4(Ar[mt][0], Ar[mt][1], Ar[mt][2], Ar[mt][3], stg + A_PL + off);
            }
            uint32_t Br[8][2];
            #pragma unroll
            for (int ntp = 0; ntp < 4; ntp++) {
                uint32_t off = b_base[ntp] + ((kb + b_colb) ^ b_mask[ntp]);
                ldsm4(Br[2 * ntp][0], Br[2 * ntp][1], Br[2 * ntp + 1][0], Br[2 * ntp + 1][1],
                      stg + B_PL + off);
            }
            #pragma unroll
            for (int mt = 0; mt < 2; mt++)
                #pragma unroll
                for (int nt = 0; nt < 8; nt++)
                    mma_fp16(acc[mt][nt], Ar[mt], Br[nt]);
        }
        __syncthreads();
    }

    const int lr = lane >> 2;
    const int lc = lane & 3;
    #pragma unroll
    for (int mt = 0; mt < 2; mt++) {
        const int gr0 = bm * BM + wm * 32 + mt * 16 + lr;
        #pragma unroll
        for (int nt = 0; nt < 8; nt++) {
            const int gc = bn * BN + wn * 64 + nt * 8 + lc * 2;
            const float b0 = __ldg(&bias[gc]);
            const float b1 = __ldg(&bias[gc + 1]);
            *(float2*)(Y + (size_t)gr0 * DMODEL + gc) =
                make_float2(acc[mt][nt][0] + b0, acc[mt][nt][1] + b1);
            *(float2*)(Y + (size_t)(gr0 + 8) * DMODEL + gc) =
                make_float2(acc[mt][nt][2] + b0, acc[mt][nt][3] + b1);
        }
    }
}

// =============================================================================
// kv partial via HMMA: C[d][e] = sum_m K[m][d]*V[m][e] over 256-m split (KSPLIT 16),
// z[d] = sum_m K[m][d] from A fragments.
// =============================================================================
__global__ __launch_bounds__(128, 1)
void kv_hmma(const __half* __restrict__ Kb, const __half* __restrict__ Vb,
             float* __restrict__ kvp, float* __restrict__ zp) {
    extern __shared__ char sm[];
    const uint32_t sbase = smem_u32(sm);
    const int tid = threadIdx.x;
    const int lane = tid & 31;
    const int wid = tid >> 5;

    const int s  = blockIdx.x % KSPLIT;
    const int bh = blockIdx.x / KSPLIT;
    const int b = bh / HEADS, h = bh % HEADS;
    const int blkbase = b * (SEQ / 128) + s * 2;

    if (tid == 0) { mbar_init(sbase, 1); mbar_init(sbase + 8, 1); }
    __syncthreads();

    auto issue = [&](int j) {
        const int st = j & 1;
        const uint32_t mb = sbase + st * 8;
        const uint32_t dst = sbase + 1024 + st * KV_STAGE;
        mbar_expect_tx(mb, 2 * BLK_BYTES);
        const size_t off = ((size_t)((blkbase + j) * NCH + h)) << 14;
        bulk_cp(dst,         (const char*)Kb + off, BLK_BYTES, mb);
        bulk_cp(dst + 16384, (const char*)Vb + off, BLK_BYTES, mb);
    };
    if (tid == 0) { issue(0); issue(1); }

    const int d0 = wid * 16;
    const int a_rloc = (lane & 7) + ((lane >> 4) << 3);
    const uint32_t a_cb = (uint32_t)(d0 * 2) + (uint32_t)(((lane >> 3) & 1) << 4);
    const uint32_t a_off = (uint32_t)(a_rloc * 128) + (a_cb ^ ((uint32_t)(a_rloc & 7) << 4));
    const int b_rloc = (lane & 7) + (((lane >> 3) & 1) << 3);
    const uint32_t b_cb0 = (uint32_t)((lane >> 4) << 4);
    uint32_t b_off[4];
    #pragma unroll
    for (int e4 = 0; e4 < 4; e4++)
        b_off[e4] = (uint32_t)(b_rloc * 128)
                  + (((uint32_t)(e4 * 32) + b_cb0) ^ ((uint32_t)(b_rloc & 7) << 4));

    float acc[8][4];
    #pragma unroll
    for (int nt = 0; nt < 8; nt++)
        #pragma unroll
        for (int i = 0; i < 4; i++) acc[nt][i] = 0.f;
    float zs0 = 0.f, zs1 = 0.f;

    #pragma unroll
    for (int j = 0; j < 2; j++) {
        mbar_wait(sbase + (j & 1) * 8, 0);
        const uint32_t bK = sbase + 1024 + (j & 1) * KV_STAGE;
        const uint32_t bV = bK + 16384;
        #pragma unroll
        for (int ks = 0; ks < 8; ks++) {
            uint32_t Ar[4];
            ldsm4t(Ar[0], Ar[1], Ar[2], Ar[3], bK + (uint32_t)(ks * 2048) + a_off);
            uint32_t Br[8][2];
            #pragma unroll
            for (int e4 = 0; e4 < 4; e4++) {
                uint32_t r0, r1, r2, r3;
                ldsm4t(r0, r1, r2, r3, bV + (uint32_t)(ks * 2048) + b_off[e4]);
                Br[2 * e4][0] = r0; Br[2 * e4][1] = r1;
                Br[2 * e4 + 1][0] = r2; Br[2 * e4 + 1][1] = r3;
            }
            #pragma unroll
            for (int nt = 0; nt < 8; nt++) mma_fp16(acc[nt], Ar, Br[nt]);
            zs0 += h2sum(Ar[0]) + h2sum(Ar[2]);
            zs1 += h2sum(Ar[1]) + h2sum(Ar[3]);
        }
    }

    zs0 += __shfl_xor_sync(0xFFFFFFFF, zs0, 1);
    zs0 += __shfl_xor_sync(0xFFFFFFFF, zs0, 2);
    zs1 += __shfl_xor_sync(0xFFFFFFFF, zs1, 1);
    zs1 += __shfl_xor_sync(0xFFFFFFFF, zs1, 2);

    const int g = lane >> 2;
    const int ec = 2 * (lane & 3);
    float* kout = kvp + (size_t)blockIdx.x * (DH * DH);
    #pragma unroll
    for (int nt = 0; nt < 8; nt++) {
        *(float2*)&kout[(d0 + g) * DH + nt * 8 + ec]     = make_float2(acc[nt][0], acc[nt][1]);
        *(float2*)&kout[(d0 + g + 8) * DH + nt * 8 + ec] = make_float2(acc[nt][2], acc[nt][3]);
    }
    if ((lane & 3) == 0) {
        zp[(size_t)blockIdx.x * DH + d0 + g]     = zs0;
        zp[(size_t)blockIdx.x * DH + d0 + g + 8] = zs1;
    }
}

// =============================================================================
// reduce partials -> kvT fp16 swizzled [e][d] + z fp32
// =============================================================================
__global__ __launch_bounds__(256)
void kv_reduce(const float* __restrict__ kvp, const float* __restrict__ zp,
               __half* __restrict__ kvT, float* __restrict__ zo) {
    const int bh = blockIdx.x;
    const int tid = threadIdx.x;
    for (int i = tid; i < DH * DH; i += 256) {
        float sum = 0.f;
        #pragma unroll
        for (int s = 0; s < KSPLIT; s++)
            sum += kvp[((size_t)bh * KSPLIT + s) * (DH * DH) + i];
        const int d = i >> 6, e = i & 63;
        const size_t off = (size_t)bh * 8192 + (uint32_t)(e * 128)
                         + (((uint32_t)(d * 2)) ^ ((uint32_t)(e & 7) << 4));
        *(__half*)((char*)kvT + off) = __float2half_rn(sum);
    }
    if (tid < DH) {
        float sum = 0.f;
        #pragma unroll
        for (int s = 0; s < KSPLIT; s++)
            sum += zp[((size_t)bh * KSPLIT + s) * DH + tid];
        zo[(size_t)bh * DH + tid] = sum;
    }
}

// =============================================================================
// attn via HMMA: out[n][e] = (sum_d Q[n][d] kvT[e][d]) / (q.z + eps).
// grid = (ROWS/128, 2): grid.y picks 8-head range.
// =============================================================================
__global__ __launch_bounds__(256, 1)
void attn_hmma(const __half* __restrict__ Qb, const __half* __restrict__ kvT,
               const float* __restrict__ z, __half* __restrict__ Sb) {
    extern __shared__ char sm[];
    __shared__ float zsm[2][64];
    const uint32_t sbase = smem_u32(sm);
    const int tid = threadIdx.x;
    const int lane = tid & 31;
    const int wid = tid >> 5;
    const int blk = blockIdx.x;
    const int h0 = blockIdx.y * 8;
    const int b = blk >> 5;

    if (tid == 0) { mbar_init(sbase, 1); mbar_init(sbase + 8, 1); }

    auto issue = [&](int hh) {
        const int h = h0 + hh;
        const int st = hh & 1;
        const uint32_t mb = sbase + st * 8;
        const uint32_t dst = sbase + 1024 + st * AT_STAGE;
        mbar_expect_tx(mb, 16384 + 8192);
        bulk_cp(dst, (const char*)Qb + (((size_t)(blk * NCH + h)) << 14), 16384, mb);
        bulk_cp(dst + 16384, (const char*)kvT + (((size_t)(b * HEADS + h)) << 13), 8192, mb);
    };
    __syncthreads();
    if (tid == 0) { issue(0); issue(1); }
    if (tid < 64) {
        zsm[0][tid] = z[(size_t)(b * HEADS + h0 + 0) * DH + tid];
        zsm[1][tid] = z[(size_t)(b * HEADS + h0 + 1) * DH + tid];
    }
    __syncthreads();

    const int row_a = wid * 16 + (lane & 15);
    const uint32_t a_base = (uint32_t)(row_a * 128);
    const uint32_t a_mask = (uint32_t)((row_a & 7) << 4);
    const uint32_t a_colb = (uint32_t)((lane >> 4) << 4);
    int nrow[4];
    #pragma unroll
    for (int ntp = 0; ntp < 4; ntp++)
        nrow[ntp] = ntp * 16 + (lane & 7) + ((lane >> 4) << 3);
    const uint32_t b_colb = (lane & 8) ? 16u : 0u;
    uint32_t b_base[4], b_mask[4];
    #pragma unroll
    for (int ntp = 0; ntp < 4; ntp++) {
        b_base[ntp] = (uint32_t)(nrow[ntp] * 128);
        b_mask[ntp] = (uint32_t)((nrow[ntp] & 7) << 4);
    }

    const int g = lane >> 2;
    const int ec = 2 * (lane & 3);

    for (int hh = 0; hh < 8; hh++) {
        const int h = h0 + hh;
        const int st = hh & 1;
        mbar_wait(sbase + st * 8, (hh >> 1) & 1);
        const uint32_t bQ = sbase + 1024 + st * AT_STAGE;
        const uint32_t bKV = bQ + 16384;

        float acc[8][4];
        #pragma unroll
        for (int nt = 0; nt < 8; nt++)
            #pragma unroll
            for (int i = 0; i < 4; i++) acc[nt][i] = 0.f;
        float den0 = 0.f, den1 = 0.f;

        #pragma unroll
        for (int ks = 0; ks < 4; ks++) {
            const uint32_t kb = (uint32_t)(ks * 32);
            uint32_t Ar[4];
            ldsm4(Ar[0], Ar[1], Ar[2], Ar[3], bQ + a_base + ((kb + a_colb) ^ a_mask));
            uint32_t Br[8][2];
            #pragma unroll
            for (int ntp = 0; ntp < 4; ntp++) {
                uint32_t off = b_base[ntp] + ((kb + b_colb) ^ b_mask[ntp]);
                ldsm4(Br[2 * ntp][0], Br[2 * ntp][1], Br[2 * ntp + 1][0], Br[2 * ntp + 1][1],
                      bKV + off);
            }
            #pragma unroll
            for (int nt = 0; nt < 8; nt++) mma_fp16(acc[nt], Ar, Br[nt]);

            const int dbase = ks * 16 + ec;
            const float z0 = zsm[st][dbase],     z1 = zsm[st][dbase + 1];
            const float z8 = zsm[st][dbase + 8], z9 = zsm[st][dbase + 9];
            float2 a0 = __half22float2(*(__half2*)&Ar[0]);
            float2 a1 = __half22float2(*(__half2*)&Ar[1]);
            float2 a2 = __half22float2(*(__half2*)&Ar[2]);
            float2 a3 = __half22float2(*(__half2*)&Ar[3]);
            den0 += a0.x * z0 + a0.y * z1 + a2.x * z8 + a2.y * z9;
            den1 += a1.x * z0 + a1.y * z1 + a3.x * z8 + a3.y * z9;
        }
        den0 += __shfl_xor_sync(0xFFFFFFFF, den0, 1);
        den0 += __shfl_xor_sync(0xFFFFFFFF, den0, 2);
        den1 += __shfl_xor_sync(0xFFFFFFFF, den1, 1);
        den1 += __shfl_xor_sync(0xFFFFFFFF, den1, 2);
        const float rinv0 = 1.0f / (den0 + EPSV);
        const float rinv1 = 1.0f / (den1 + EPSV);

        const size_t blkb = ((size_t)(blk * NCH + h)) << 14;
        const uint32_t ra = (uint32_t)(wid * 16 + g);
        const uint32_t rb = ra + 8;
        #pragma unroll
        for (int nt = 0; nt < 8; nt++) {
            const uint32_t colb = (uint32_t)((nt * 8 + ec) * 2);
            __half2 p0 = __floats2half2_rn(acc[nt][0] * rinv0, acc[nt][1] * rinv0);
            __half2 p1 = __floats2half2_rn(acc[nt][2] * rinv1, acc[nt][3] * rinv1);
            *(uint32_t*)((char*)Sb + blkb + ra * 128 + (colb ^ ((ra & 7) << 4))) =
                *(uint32_t*)&p0;
            *(uint32_t*)((char*)Sb + blkb + rb * 128 + (colb ^ ((rb & 7) << 4))) =
                *(uint32_t*)&p1;
        }
        __syncthreads();
        if (tid == 0 && hh + 2 < 8) issue(hh + 2);
        if (tid < 64 && hh + 2 < 8)
            zsm[st][tid] = z[(size_t)(b * HEADS + h0 + hh + 2) * DH + tid];
    }
}

// =============================================================================
extern "C" void kernel_launch(void* const* d_in, const int* in_sizes, int n_in,
                              void* d_out, int out_size) {
    const float* queries = (const float*)d_in[0];
    const float* keys    = (const float*)d_in[1];
    const float* values  = (const float*)d_in[2];
    const float* wq = (const float*)d_in[3];
    const float* bq = (const float*)d_in[4];
    const float* wk = (const float*)d_in[5];
    const float* bk = (const float*)d_in[6];
    const float* wv = (const float*)d_in[7];
    const float* bv = (const float*)d_in[8];
    const float* wo = (const float*)d_in[9];
    const float* bo = (const float*)d_in[10];
    float* out = (float*)d_out;

    __half *Xbp, *Abp, *Wbp, *Qbp, *Kbp, *Vbp, *kvTp;
    float *kvp, *zp, *zb;
    cudaGetSymbolAddress((void**)&Xbp, g_Xb);
    cudaGetSymbolAddress((void**)&Abp, g_Ab);
    cudaGetSymbolAddress((void**)&Wbp, g_Wb);
    cudaGetSymbolAddress((void**)&Qbp, g_Qb);
    cudaGetSymbolAddress((void**)&Kbp, g_Kb);
    cudaGetSymbolAddress((void**)&Vbp, g_Vb);
    cudaGetSymbolAddress((void**)&kvTp, g_kvT);
    cudaGetSymbolAddress((void**)&kvp, g_kvp);
    cudaGetSymbolAddress((void**)&zp,  g_zp);
    cudaGetSymbolAddress((void**)&zb,  g_z);

    cudaFuncSetAttribute(gemm_qkv, cudaFuncAttributeMaxDynamicSharedMemorySize, SMEM_BYTES);
    cudaFuncSetAttribute(gemm_out, cudaFuncAttributeMaxDynamicSharedMemorySize, SMEM_BYTES);
    cudaFuncSetAttribute(kv_hmma,   cudaFuncAttributeMaxDynamicSharedMemorySize, KV_SMEM);
    cudaFuncSetAttribute(attn_hmma, cudaFuncAttributeMaxDynamicSharedMemorySize, AT_SMEM);

    const int WSZ = DMODEL * DMODEL;
    const int XN8 = ROWS * DMODEL / 8;
    const int WN8 = WSZ / 8;

    dim3 gb(GTHREADS);

    // weights -> blocked fp16, one launch (z = 4 tensors)
    cvt_swz_multi<<<dim3(512, 1, 4), 256>>>(wq, wk, wv, wo, Wbp, (size_t)WSZ, WN8);
    // activations -> blocked fp16, one launch (z = 3 tensors)
    cvt_swz_multi<<<dim3(2048, 1, 3), 256>>>(queries, keys, values, nullptr,
                                             Xbp, ASTRIDE, XN8);

    // merged QKV projections (1536 CTAs of 512 threads)
    gemm_qkv<<<dim3(DMODEL / BN, ROWS / BM, 3), gb, SMEM_BYTES>>>(
        Xbp, Wbp, bq, bk, bv, Qbp, Kbp, Vbp);

    kv_hmma  <<<BATCH * HEADS * KSPLIT, 128, KV_SMEM>>>(Kbp, Vbp, kvp, zp);
    kv_reduce<<<BATCH * HEADS, 256>>>(kvp, zp, kvTp, zb);
    attn_hmma<<<dim3(ROWS / 128, 2), 256, AT_SMEM>>>(Qbp, kvTp, zb, Abp);

    // output projection (fp32 out)
    gemm_out<<<dim3(DMODEL / BN, ROWS / BM), gb, SMEM_BYTES>>>(
        Abp, Wbp + 3 * WSZ, bo, out);
}

// round 13
// speedup vs baseline: 1.1520x; 1.1520x over previous
#include <cuda_runtime.h>
#include <cuda_fp16.h>
#include <cstdint>

// Problem constants (fixed by reference)
#define DMODEL 1024
#define HEADS  16
#define DH     64
#define BATCH  4
#define SEQ    4096
#define ROWS   (BATCH * SEQ)   // 16384
#define KSPLIT 16
#define EPSV   1e-6f

// GEMM tiling (HMMA mma.sync; tcgen05 unavailable on compute_103 virtual arch)
#define BM 128
#define BN 128
#define NCH (DMODEL / 64)       // 16 chunks of 64 fp16 per 1024-row
#define GTHREADS 256
#define STAGES 3                // 99KB smem -> 2 CTAs/SM

// Blocked-swizzled fp16 layout: 16KB block per (row-tile of 128, 64-col chunk).
#define BLK_BYTES 16384

#define A_PL 0
#define B_PL 16384
#define STAGE 32768
#define SMEM_BYTES (1024 + STAGES * STAGE)   // 99328

#define KV_STAGE 32768                        // K 16KB + V 16KB
#define KV_SMEM  (1024 + 2 * KV_STAGE)        // 66560
#define AT_STAGE 24576                        // Q 16KB + kvT 8KB
#define AT_SMEM  (1024 + 2 * AT_STAGE)        // 50176

#define ASTRIDE ((size_t)ROWS * DMODEL)

// ---------------- scratch (device globals; no allocation allowed) ------------
__device__ __half g_Xb[3 * ROWS * DMODEL];          // blocked q/k/v inputs
__device__ __half g_Ab[ROWS * DMODEL];              // S (blocked)
__device__ __half g_Wb[4 * DMODEL * DMODEL];        // blocked wq,wk,wv,wo
__device__ __half g_Qb[ROWS * DMODEL];              // Q fp16 blocked
__device__ __half g_Kb[ROWS * DMODEL];              // K fp16 blocked
__device__ __half g_Vb[ROWS * DMODEL];              // V fp16 blocked
__device__ float g_kvp[BATCH * HEADS * KSPLIT * DH * DH];
__device__ float g_zp [BATCH * HEADS * KSPLIT * DH];
__device__ __half g_kvT[BATCH * HEADS * DH * DH];   // kv^T fp16 swizzled [e][d]
__device__ float g_z  [BATCH * HEADS * DH];

// =============================== helpers ====================================
__device__ __forceinline__ uint32_t smem_u32(const void* p) {
    uint32_t a;
    asm("{ .reg .u64 t; cvta.to.shared.u64 t, %1; cvt.u32.u64 %0, t; }"
        : "=r"(a) : "l"(p));
    return a;
}
__device__ __forceinline__ void ldsm4(uint32_t& r0, uint32_t& r1, uint32_t& r2,
                                      uint32_t& r3, uint32_t addr) {
    asm volatile("ldmatrix.sync.aligned.m8n8.x4.shared.b16 {%0,%1,%2,%3}, [%4];"
                 : "=r"(r0), "=r"(r1), "=r"(r2), "=r"(r3) : "r"(addr));
}
__device__ __forceinline__ void ldsm4t(uint32_t& r0, uint32_t& r1, uint32_t& r2,
                                       uint32_t& r3, uint32_t addr) {
    asm volatile("ldmatrix.sync.aligned.m8n8.x4.trans.shared.b16 {%0,%1,%2,%3}, [%4];"
                 : "=r"(r0), "=r"(r1), "=r"(r2), "=r"(r3) : "r"(addr));
}
__device__ __forceinline__ void mma_fp16(float* c, const uint32_t* a, const uint32_t* b) {
    asm volatile(
        "mma.sync.aligned.m16n8k16.row.col.f32.f16.f16.f32 "
        "{%0,%1,%2,%3}, {%4,%5,%6,%7}, {%8,%9}, {%0,%1,%2,%3};"
        : "+f"(c[0]), "+f"(c[1]), "+f"(c[2]), "+f"(c[3])
        : "r"(a[0]), "r"(a[1]), "r"(a[2]), "r"(a[3]), "r"(b[0]), "r"(b[1]));
}
__device__ __forceinline__ void mbar_init(uint32_t addr, uint32_t cnt) {
    asm volatile("mbarrier.init.shared.b64 [%0], %1;" :: "r"(addr), "r"(cnt) : "memory");
}
__device__ __forceinline__ void mbar_expect_tx(uint32_t addr, uint32_t bytes) {
    asm volatile("mbarrier.arrive.expect_tx.shared.b64 _, [%0], %1;"
                 :: "r"(addr), "r"(bytes) : "memory");
}
__device__ __forceinline__ void mbar_wait(uint32_t addr, uint32_t parity) {
    asm volatile(
        "{\n\t.reg .pred P;\n"
        "W%=:\n\t"
        "mbarrier.try_wait.parity.acquire.cta.shared::cta.b64 P, [%0], %1, 0x989680;\n\t"
        "@!P bra W%=;\n\t"
        "}"
        :: "r"(addr), "r"(parity) : "memory");
}
__device__ __forceinline__ void bulk_cp(uint32_t sdst, const void* gsrc,
                                        uint32_t bytes, uint32_t mbar) {
    asm volatile(
        "cp.async.bulk.shared::cta.global.mbarrier::complete_tx::bytes [%0], [%1], %2, [%3];"
        :: "r"(sdst), "l"(gsrc), "r"(bytes), "r"(mbar) : "memory");
}
__device__ __forceinline__ uint2 cvt_f16x4(float4 v) {
    __half2 p01 = __floats2half2_rn(v.x, v.y);
    __half2 p23 = __floats2half2_rn(v.z, v.w);
    return make_uint2(*(uint32_t*)&p01, *(uint32_t*)&p23);
}
__device__ __forceinline__ float h2sum(uint32_t r) {
    float2 f = __half22float2(*(__half2*)&r);
    return f.x + f.y;
}

// =============================================================================
// fp32 [rows][1024] -> blocked-swizzled fp16; up to 4 tensors per launch (z).
// Each thread handles 8 floats -> ONE 16B store (16B = swizzle atom, aligned).
// =============================================================================
__global__ __launch_bounds__(256)
void cvt_swz_multi(const float* __restrict__ s0, const float* __restrict__ s1,
                   const float* __restrict__ s2, const float* __restrict__ s3,
                   __half* __restrict__ dst, size_t dstride, int n8) {
    const float* src = (blockIdx.z == 0) ? s0 : (blockIdx.z == 1) ? s1
                     : (blockIdx.z == 2) ? s2 : s3;
    __half* d = dst + (size_t)blockIdx.z * dstride;
    for (int i = blockIdx.x * 256 + threadIdx.x; i < n8; i += gridDim.x * 256) {
        const int grow = i >> 7;
        const int gcol = (i & 127) * 8;
        const int blk  = grow >> 7;
        const int r    = grow & 127;
        const int c    = gcol >> 6;
        const uint32_t colb = (uint32_t)((gcol & 63) * 2);
        const size_t off = ((size_t)(blk * NCH + c) << 14)
                         + (uint32_t)(r * 128) + (colb ^ ((uint32_t)(r & 7) << 4));
        float4 va = ((const float4*)src)[2 * i];
        float4 vb = ((const float4*)src)[2 * i + 1];
        uint2 pa = cvt_f16x4(va);
        uint2 pb = cvt_f16x4(vb);
        *(uint4*)((char*)d + off) = make_uint4(pa.x, pa.y, pb.x, pb.y);
    }
}

// =============================================================================
// Merged QKV projection GEMM (NT): grid.z selects {input, weight, bias, out, phi}.
// CTA 128x128, 256 threads, 3 stages -> 2 CTAs/SM.
// =============================================================================
__global__ __launch_bounds__(GTHREADS, 2)
void gemm_qkv(const __half* __restrict__ Xb, const __half* __restrict__ Wb,
              const float* __restrict__ bq, const float* __restrict__ bk,
              const float* __restrict__ bv,
              __half* __restrict__ Qb, __half* __restrict__ Kb,
              __half* __restrict__ Vb) {
    extern __shared__ char sm[];
    const uint32_t sbase = smem_u32(sm);
    const int tid = threadIdx.x;
    const int lane = tid & 31;
    const int wid = tid >> 5;
    const int wm = wid & 3;
    const int wn = wid >> 2;
    const int bm = blockIdx.y;
    const int bn = blockIdx.x;
    const int zi = blockIdx.z;

    const __half* Ab = Xb + (size_t)zi * ASTRIDE;
    const __half* Bb = Wb + (size_t)zi * (DMODEL * DMODEL);
    const float* bias = (zi == 0) ? bq : (zi == 1) ? bk : bv;
    __half* Yh = (zi == 0) ? Qb : (zi == 1) ? Kb : Vb;
    const bool phi = (zi != 2);

    if (tid == 0) {
        #pragma unroll
        for (int s = 0; s < STAGES; s++) mbar_init(sbase + s * 8, 1);
    }
    __syncthreads();

    const char* gAb = (const char*)Ab + ((size_t)(bm * NCH) << 14);
    const char* gBb = (const char*)Bb + ((size_t)(bn * NCH) << 14);

    int row_a[2];
    row_a[0] = wm * 32 + (lane & 15);
    row_a[1] = row_a[0] + 16;
    const uint32_t a_colb = (uint32_t)((lane >> 4) << 4);
    uint32_t a_base[2], a_mask[2];
    #pragma unroll
    for (int mt = 0; mt < 2; mt++) {
        a_base[mt] = (uint32_t)(row_a[mt] * 128);
        a_mask[mt] = (uint32_t)((row_a[mt] & 7) << 4);
    }
    int nrow[4];
    #pragma unroll
    for (int ntp = 0; ntp < 4; ntp++)
        nrow[ntp] = wn * 64 + ntp * 16 + (lane & 7) + ((lane >> 4) << 3);
    const uint32_t b_colb = (lane & 8) ? 16u : 0u;
    uint32_t b_base[4], b_mask[4];
    #pragma unroll
    for (int ntp = 0; ntp < 4; ntp++) {
        b_base[ntp] = (uint32_t)(nrow[ntp] * 128);
        b_mask[ntp] = (uint32_t)((nrow[ntp] & 7) << 4);
    }

    float acc[2][8][4];
    #pragma unroll
    for (int mt = 0; mt < 2; mt++)
        #pragma unroll
        for (int nt = 0; nt < 8; nt++)
            #pragma unroll
            for (int i = 0; i < 4; i++) acc[mt][nt][i] = 0.f;

    auto issue = [&](int c) {
        const int s = c % STAGES;
        const uint32_t mb = sbase + s * 8;
        const uint32_t st = sbase + 1024 + s * STAGE;
        mbar_expect_tx(mb, 2 * BLK_BYTES);
        bulk_cp(st + A_PL, gAb + ((size_t)c << 14), BLK_BYTES, mb);
        bulk_cp(st + B_PL, gBb + ((size_t)c << 14), BLK_BYTES, mb);
    };

    if (tid == 0) { issue(0); issue(1); }

    for (int c = 0; c < NCH; c++) {
        mbar_wait(sbase + (c % STAGES) * 8, (c / STAGES) & 1);
        if (tid == 0 && c + 2 < NCH) issue(c + 2);

        const uint32_t stg = sbase + 1024 + (uint32_t)((c % STAGES) * STAGE);
        #pragma unroll
        for (int ks = 0; ks < 4; ks++) {
            const uint32_t kb = (uint32_t)(ks * 32);
            uint32_t Ar[2][4];
            #pragma unroll
            for (int mt = 0; mt < 2; mt++) {
                uint32_t off = a_base[mt] + ((kb + a_colb) ^ a_mask[mt]);
                ldsm4(Ar[mt][0], Ar[mt][1], Ar[mt][2], Ar[mt][3], stg + A_PL + off);
            }
            uint32_t Br[8][2];
            #pragma unroll
            for (int ntp = 0; ntp < 4; ntp++) {
                uint32_t off = b_base[ntp] + ((kb + b_colb) ^ b_mask[ntp]);
                ldsm4(Br[2 * ntp][0], Br[2 * ntp][1], Br[2 * ntp + 1][0], Br[2 * ntp + 1][1],
                      stg + B_PL + off);
            }
            #pragma unroll
            for (int mt = 0; mt < 2; mt++)
                #pragma unroll
                for (int nt = 0; nt < 8; nt++)
                    mma_fp16(acc[mt][nt], Ar[mt], Br[nt]);
        }
        __syncthreads();
    }

    // ---- epilogue: bias (+ phi), store fp16 blocked ----
    const int lr = lane >> 2;
    const int lc = lane & 3;
    #pragma unroll
    for (int mt = 0; mt < 2; mt++) {
        const int r0l = wm * 32 + mt * 16 + lr;
        #pragma unroll
        for (int nt = 0; nt < 8; nt++) {
            const int gc = bn * BN + wn * 64 + nt * 8 + lc * 2;
            const float b0 = __ldg(&bias[gc]);
            const float b1 = __ldg(&bias[gc + 1]);
            float o00 = acc[mt][nt][0] + b0;
            float o01 = acc[mt][nt][1] + b1;
            float o10 = acc[mt][nt][2] + b0;
            float o11 = acc[mt][nt][3] + b1;
            if (phi) {
                o00 = (o00 > 0.f) ? (o00 + 1.f) : __expf(o00);
                o01 = (o01 > 0.f) ? (o01 + 1.f) : __expf(o01);
                o10 = (o10 > 0.f) ? (o10 + 1.f) : __expf(o10);
                o11 = (o11 > 0.f) ? (o11 + 1.f) : __expf(o11);
            }
            const int cch = gc >> 6;
            const uint32_t colb = (uint32_t)((gc & 63) * 2);
            const size_t blkb = ((size_t)(bm * NCH + cch)) << 14;
            __half2 p0 = __floats2half2_rn(o00, o01);
            __half2 p1 = __floats2half2_rn(o10, o11);
            const uint32_t ra = (uint32_t)r0l, rb = (uint32_t)(r0l + 8);
            *(uint32_t*)((char*)Yh + blkb + ra * 128 + (colb ^ ((ra & 7) << 4))) =
                *(uint32_t*)&p0;
            *(uint32_t*)((char*)Yh + blkb + rb * 128 + (colb ^ ((rb & 7) << 4))) =
                *(uint32_t*)&p1;
        }
    }
}

// =============================================================================
// Output projection GEMM (fp32 row-major out), same engine.
// =============================================================================
__global__ __launch_bounds__(GTHREADS, 2)
void gemm_out(const __half* __restrict__ Ab, const __half* __restrict__ Bb,
              const float* __restrict__ bias, float* __restrict__ Y) {
    extern __shared__ char sm[];
    const uint32_t sbase = smem_u32(sm);
    const int tid = threadIdx.x;
    const int lane = tid & 31;
    const int wid = tid >> 5;
    const int wm = wid & 3;
    const int wn = wid >> 2;
    const int bm = blockIdx.y;
    const int bn = blockIdx.x;

    if (tid == 0) {
        #pragma unroll
        for (int s = 0; s < STAGES; s++) mbar_init(sbase + s * 8, 1);
    }
    __syncthreads();

    const char* gAb = (const char*)Ab + ((size_t)(bm * NCH) << 14);
    const char* gBb = (const char*)Bb + ((size_t)(bn * NCH) << 14);

    int row_a[2];
    row_a[0] = wm * 32 + (lane & 15);
    row_a[1] = row_a[0] + 16;
    const uint32_t a_colb = (uint32_t)((lane >> 4) << 4);
    uint32_t a_base[2], a_mask[2];
    #pragma unroll
    for (int mt = 0; mt < 2; mt++) {
        a_base[mt] = (uint32_t)(row_a[mt] * 128);
        a_mask[mt] = (uint32_t)((row_a[mt] & 7) << 4);
    }
    int nrow[4];
    #pragma unroll
    for (int ntp = 0; ntp < 4; ntp++)
        nrow[ntp] = wn * 64 + ntp * 16 + (lane & 7) + ((lane >> 4) << 3);
    const uint32_t b_colb = (lane & 8) ? 16u : 0u;
    uint32_t b_base[4], b_mask[4];
    #pragma unroll
    for (int ntp = 0; ntp < 4; ntp++) {
        b_base[ntp] = (uint32_t)(nrow[ntp] * 128);
        b_mask[ntp] = (uint32_t)((nrow[ntp] & 7) << 4);
    }

    float acc[2][8][4];
    #pragma unroll
    for (int mt = 0; mt < 2; mt++)
        #pragma unroll
        for (int nt = 0; nt < 8; nt++)
            #pragma unroll
            for (int i = 0; i < 4; i++) acc[mt][nt][i] = 0.f;

    auto issue = [&](int c) {
        const int s = c % STAGES;
        const uint32_t mb = sbase + s * 8;
        const uint32_t st = sbase + 1024 + s * STAGE;
        mbar_expect_tx(mb, 2 * BLK_BYTES);
        bulk_cp(st + A_PL, gAb + ((size_t)c << 14), BLK_BYTES, mb);
        bulk_cp(st + B_PL, gBb + ((size_t)c << 14), BLK_BYTES, mb);
    };

    if (tid == 0) { issue(0); issue(1); }

    for (int c = 0; c < NCH; c++) {
        mbar_wait(sbase + (c % STAGES) * 8, (c / STAGES) & 1);
        if (tid == 0 && c + 2 < NCH) issue(c + 2);

        const uint32_t stg = sbase + 1024 + (uint32_t)((c % STAGES) * STAGE);
        #pragma unroll
        for (int ks = 0; ks < 4; ks++) {
            const uint32_t kb = (uint32_t)(ks * 32);
            uint32_t Ar[2][4];
            #pragma unroll
            for (int mt = 0; mt < 2; mt++) {
                uint32_t off = a_base[mt] + ((kb + a_colb) ^ a_mask[mt]);
                ldsm4(Ar[mt][0], Ar[mt][1], Ar[mt][2], Ar[mt][3], stg + A_PL + off);
            }
            uint32_t Br[8][2];
            #pragma unroll
            for (int ntp = 0; ntp < 4; ntp++) {
                uint32_t off = b_base[ntp] + ((kb + b_colb) ^ b_mask[ntp]);
                ldsm4(Br[2 * ntp][0], Br[2 * ntp][1], Br[2 * ntp + 1][0], Br[2 * ntp + 1][1],
                      stg + B_PL + off);
            }
            #pragma unroll
            for (int mt = 0; mt < 2; mt++)
                #pragma unroll
                for (int nt = 0; nt < 8; nt++)
                    mma_fp16(acc[mt][nt], Ar[mt], Br[nt]);
        }
        __syncthreads();
    }

    const int lr = lane >> 2;
    const int lc = lane & 3;
    #pragma unroll
    for (int mt = 0; mt < 2; mt++) {
        const int gr0 = bm * BM + wm * 32 + mt * 16 + lr;
        #pragma unroll
        for (int nt = 0; nt < 8; nt++) {
            const int gc = bn * BN + wn * 64 + nt * 8 + lc * 2;
            const float b0 = __ldg(&bias[gc]);
            const float b1 = __ldg(&bias[gc + 1]);
            *(float2*)(Y + (size_t)gr0 * DMODEL + gc) =
                make_float2(acc[mt][nt][0] + b0, acc[mt][nt][1] + b1);
            *(float2*)(Y + (size_t)(gr0 + 8) * DMODEL + gc) =
                make_float2(acc[mt][nt][2] + b0, acc[mt][nt][3] + b1);
        }
    }
}

// =============================================================================
// kv partial via HMMA, 256 threads / 8 warps (e-split for occupancy):
// warp w: d-range = (w&3)*16, e-half = (w>>2)*32.
// C[d][e] = sum_m K[m][d]*V[m][e] over 256-m split; z from A fragments (e-low warps).
// =============================================================================
__global__ __launch_bounds__(256, 1)
void kv_hmma(const __half* __restrict__ Kb, const __half* __restrict__ Vb,
             float* __restrict__ kvp, float* __restrict__ zp) {
    extern __shared__ char sm[];
    const uint32_t sbase = smem_u32(sm);
    const int tid = threadIdx.x;
    const int lane = tid & 31;
    const int wid = tid >> 5;

    const int s  = blockIdx.x % KSPLIT;
    const int bh = blockIdx.x / KSPLIT;
    const int b = bh / HEADS, h = bh % HEADS;
    const int blkbase = b * (SEQ / 128) + s * 2;

    if (tid == 0) { mbar_init(sbase, 1); mbar_init(sbase + 8, 1); }
    __syncthreads();

    auto issue = [&](int j) {
        const int st = j & 1;
        const uint32_t mb = sbase + st * 8;
        const uint32_t dst = sbase + 1024 + st * KV_STAGE;
        mbar_expect_tx(mb, 2 * BLK_BYTES);
        const size_t off = ((size_t)((blkbase + j) * NCH + h)) << 14;
        bulk_cp(dst,         (const char*)Kb + off, BLK_BYTES, mb);
        bulk_cp(dst + 16384, (const char*)Vb + off, BLK_BYTES, mb);
    };
    if (tid == 0) { issue(0); issue(1); }

    const int d0 = (wid & 3) * 16;
    const int eh = wid >> 2;              // 0 or 1: e-half
    const int a_rloc = (lane & 7) + ((lane >> 4) << 3);
    const uint32_t a_cb = (uint32_t)(d0 * 2) + (uint32_t)(((lane >> 3) & 1) << 4);
    const uint32_t a_off = (uint32_t)(a_rloc * 128) + (a_cb ^ ((uint32_t)(a_rloc & 7) << 4));
    const int b_rloc = (lane & 7) + (((lane >> 3) & 1) << 3);
    const uint32_t b_cb0 = (uint32_t)((lane >> 4) << 4);
    uint32_t b_off[2];
    #pragma unroll
    for (int e4 = 0; e4 < 2; e4++)
        b_off[e4] = (uint32_t)(b_rloc * 128)
                  + (((uint32_t)((eh * 2 + e4) * 32) + b_cb0) ^ ((uint32_t)(b_rloc & 7) << 4));

    float acc[4][4];
    #pragma unroll
    for (int nt = 0; nt < 4; nt++)
        #pragma unroll
        for (int i = 0; i < 4; i++) acc[nt][i] = 0.f;
    float zs0 = 0.f, zs1 = 0.f;

    #pragma unroll
    for (int j = 0; j < 2; j++) {
        mbar_wait(sbase + (j & 1) * 8, 0);
        const uint32_t bK = sbase + 1024 + (j & 1) * KV_STAGE;
        const uint32_t bV = bK + 16384;
        #pragma unroll
        for (int ks = 0; ks < 8; ks++) {
            uint32_t Ar[4];
            ldsm4t(Ar[0], Ar[1], Ar[2], Ar[3], bK + (uint32_t)(ks * 2048) + a_off);
            uint32_t Br[4][2];
            #pragma unroll
            for (int e4 = 0; e4 < 2; e4++) {
                uint32_t r0, r1, r2, r3;
                ldsm4t(r0, r1, r2, r3, bV + (uint32_t)(ks * 2048) + b_off[e4]);
                Br[2 * e4][0] = r0; Br[2 * e4][1] = r1;
                Br[2 * e4 + 1][0] = r2; Br[2 * e4 + 1][1] = r3;
            }
            #pragma unroll
            for (int nt = 0; nt < 4; nt++) mma_fp16(acc[nt], Ar, Br[nt]);
            if (eh == 0) {
                zs0 += h2sum(Ar[0]) + h2sum(Ar[2]);
                zs1 += h2sum(Ar[1]) + h2sum(Ar[3]);
            }
        }
    }

    const int g = lane >> 2;
    const int ec = 2 * (lane & 3);
    float* kout = kvp + (size_t)blockIdx.x * (DH * DH);
    #pragma unroll
    for (int nt = 0; nt < 4; nt++) {
        const int e = eh * 32 + nt * 8 + ec;
        *(float2*)&kout[(d0 + g) * DH + e]     = make_float2(acc[nt][0], acc[nt][1]);
        *(float2*)&kout[(d0 + g + 8) * DH + e] = make_float2(acc[nt][2], acc[nt][3]);
    }
    if (eh == 0) {
        zs0 += __shfl_xor_sync(0xFFFFFFFF, zs0, 1);
        zs0 += __shfl_xor_sync(0xFFFFFFFF, zs0, 2);
        zs1 += __shfl_xor_sync(0xFFFFFFFF, zs1, 1);
        zs1 += __shfl_xor_sync(0xFFFFFFFF, zs1, 2);
        if ((lane & 3) == 0) {
            zp[(size_t)blockIdx.x * DH + d0 + g]     = zs0;
            zp[(size_t)blockIdx.x * DH + d0 + g + 8] = zs1;
        }
    }
}

// =============================================================================
// reduce partials -> kvT fp16 swizzled [e][d] + z fp32
// =============================================================================
__global__ __launch_bounds__(256)
void kv_reduce(const float* __restrict__ kvp, const float* __restrict__ zp,
               __half* __restrict__ kvT, float* __restrict__ zo) {
    const int bh = blockIdx.x;
    const int tid = threadIdx.x;
    for (int i = tid; i < DH * DH; i += 256) {
        float sum = 0.f;
        #pragma unroll
        for (int s = 0; s < KSPLIT; s++)
            sum += kvp[((size_t)bh * KSPLIT + s) * (DH * DH) + i];
        const int d = i >> 6, e = i & 63;
        const size_t off = (size_t)bh * 8192 + (uint32_t)(e * 128)
                         + (((uint32_t)(d * 2)) ^ ((uint32_t)(e & 7) << 4));
        *(__half*)((char*)kvT + off) = __float2half_rn(sum);
    }
    if (tid < DH) {
        float sum = 0.f;
        #pragma unroll
        for (int s = 0; s < KSPLIT; s++)
            sum += zp[((size_t)bh * KSPLIT + s) * DH + tid];
        zo[(size_t)bh * DH + tid] = sum;
    }
}

// =============================================================================
// attn via HMMA: out[n][e] = (sum_d Q[n][d] kvT[e][d]) / (q.z + eps).
// grid = (ROWS/128, 2): grid.y picks 8-head range.
// =============================================================================
__global__ __launch_bounds__(256, 1)
void attn_hmma(const __half* __restrict__ Qb, const __half* __restrict__ kvT,
               const float* __restrict__ z, __half* __restrict__ Sb) {
    extern __shared__ char sm[];
    __shared__ float zsm[2][64];
    const uint32_t sbase = smem_u32(sm);
    const int tid = threadIdx.x;
    const int lane = tid & 31;
    const int wid = tid >> 5;
    const int blk = blockIdx.x;
    const int h0 = blockIdx.y * 8;
    const int b = blk >> 5;

    if (tid == 0) { mbar_init(sbase, 1); mbar_init(sbase + 8, 1); }

    auto issue = [&](int hh) {
        const int h = h0 + hh;
        const int st = hh & 1;
        const uint32_t mb = sbase + st * 8;
        const uint32_t dst = sbase + 1024 + st * AT_STAGE;
        mbar_expect_tx(mb, 16384 + 8192);
        bulk_cp(dst, (const char*)Qb + (((size_t)(blk * NCH + h)) << 14), 16384, mb);
        bulk_cp(dst + 16384, (const char*)kvT + (((size_t)(b * HEADS + h)) << 13), 8192, mb);
    };
    __syncthreads();
    if (tid == 0) { issue(0); issue(1); }
    if (tid < 64) {
        zsm[0][tid] = z[(size_t)(b * HEADS + h0 + 0) * DH + tid];
        zsm[1][tid] = z[(size_t)(b * HEADS + h0 + 1) * DH + tid];
    }
    __syncthreads();

    const int row_a = wid * 16 + (lane & 15);
    const uint32_t a_base = (uint32_t)(row_a * 128);
    const uint32_t a_mask = (uint32_t)((row_a & 7) << 4);
    const uint32_t a_colb = (uint32_t)((lane >> 4) << 4);
    int nrow[4];
    #pragma unroll
    for (int ntp = 0; ntp < 4; ntp++)
        nrow[ntp] = ntp * 16 + (lane & 7) + ((lane >> 4) << 3);
    const uint32_t b_colb = (lane & 8) ? 16u : 0u;
    uint32_t b_base[4], b_mask[4];
    #pragma unroll
    for (int ntp = 0; ntp < 4; ntp++) {
        b_base[ntp] = (uint32_t)(nrow[ntp] * 128);
        b_mask[ntp] = (uint32_t)((nrow[ntp] & 7) << 4);
    }

    const int g = lane >> 2;
    const int ec = 2 * (lane & 3);

    for (int hh = 0; hh < 8; hh++) {
        const int h = h0 + hh;
        const int st = hh & 1;
        mbar_wait(sbase + st * 8, (hh >> 1) & 1);
        const uint32_t bQ = sbase + 1024 + st * AT_STAGE;
        const uint32_t bKV = bQ + 16384;

        float acc[8][4];
        #pragma unroll
        for (int nt = 0; nt < 8; nt++)
            #pragma unroll
            for (int i = 0; i < 4; i++) acc[nt][i] = 0.f;
        float den0 = 0.f, den1 = 0.f;

        #pragma unroll
        for (int ks = 0; ks < 4; ks++) {
            const uint32_t kb = (uint32_t)(ks * 32);
            uint32_t Ar[4];
            ldsm4(Ar[0], Ar[1], Ar[2], Ar[3], bQ + a_base + ((kb + a_colb) ^ a_mask));
            uint32_t Br[8][2];
            #pragma unroll
            for (int ntp = 0; ntp < 4; ntp++) {
                uint32_t off = b_base[ntp] + ((kb + b_colb) ^ b_mask[ntp]);
                ldsm4(Br[2 * ntp][0], Br[2 * ntp][1], Br[2 * ntp + 1][0], Br[2 * ntp + 1][1],
                      bKV + off);
            }
            #pragma unroll
            for (int nt = 0; nt < 8; nt++) mma_fp16(acc[nt], Ar, Br[nt]);

            const int dbase = ks * 16 + ec;
            const float z0 = zsm[st][dbase],     z1 = zsm[st][dbase + 1];
            const float z8 = zsm[st][dbase + 8], z9 = zsm[st][dbase + 9];
            float2 a0 = __half22float2(*(__half2*)&Ar[0]);
            float2 a1 = __half22float2(*(__half2*)&Ar[1]);
            float2 a2 = __half22float2(*(__half2*)&Ar[2]);
            float2 a3 = __half22float2(*(__half2*)&Ar[3]);
            den0 += a0.x * z0 + a0.y * z1 + a2.x * z8 + a2.y * z9;
            den1 += a1.x * z0 + a1.y * z1 + a3.x * z8 + a3.y * z9;
        }
        den0 += __shfl_xor_sync(0xFFFFFFFF, den0, 1);
        den0 += __shfl_xor_sync(0xFFFFFFFF, den0, 2);
        den1 += __shfl_xor_sync(0xFFFFFFFF, den1, 1);
        den1 += __shfl_xor_sync(0xFFFFFFFF, den1, 2);
        const float rinv0 = 1.0f / (den0 + EPSV);
        const float rinv1 = 1.0f / (den1 + EPSV);

        const size_t blkb = ((size_t)(blk * NCH + h)) << 14;
        const uint32_t ra = (uint32_t)(wid * 16 + g);
        const uint32_t rb = ra + 8;
        #pragma unroll
        for (int nt = 0; nt < 8; nt++) {
            const uint32_t colb = (uint32_t)((nt * 8 + ec) * 2);
            __half2 p0 = __floats2half2_rn(acc[nt][0] * rinv0, acc[nt][1] * rinv0);
            __half2 p1 = __floats2half2_rn(acc[nt][2] * rinv1, acc[nt][3] * rinv1);
            *(uint32_t*)((char*)Sb + blkb + ra * 128 + (colb ^ ((ra & 7) << 4))) =
                *(uint32_t*)&p0;
            *(uint32_t*)((char*)Sb + blkb + rb * 128 + (colb ^ ((rb & 7) << 4))) =
                *(uint32_t*)&p1;
        }
        __syncthreads();
        if (tid == 0 && hh + 2 < 8) issue(hh + 2);
        if (tid < 64 && hh + 2 < 8)
            zsm[st][tid] = z[(size_t)(b * HEADS + h0 + hh + 2) * DH + tid];
    }
}

// =============================================================================
extern "C" void kernel_launch(void* const* d_in, const int* in_sizes, int n_in,
                              void* d_out, int out_size) {
    const float* queries = (const float*)d_in[0];
    const float* keys    = (const float*)d_in[1];
    const float* values  = (const float*)d_in[2];
    const float* wq = (const float*)d_in[3];
    const float* bq = (const float*)d_in[4];
    const float* wk = (const float*)d_in[5];
    const float* bk = (const float*)d_in[6];
    const float* wv = (const float*)d_in[7];
    const float* bv = (const float*)d_in[8];
    const float* wo = (const float*)d_in[9];
    const float* bo = (const float*)d_in[10];
    float* out = (float*)d_out;

    __half *Xbp, *Abp, *Wbp, *Qbp, *Kbp, *Vbp, *kvTp;
    float *kvp, *zp, *zb;
    cudaGetSymbolAddress((void**)&Xbp, g_Xb);
    cudaGetSymbolAddress((void**)&Abp, g_Ab);
    cudaGetSymbolAddress((void**)&Wbp, g_Wb);
    cudaGetSymbolAddress((void**)&Qbp, g_Qb);
    cudaGetSymbolAddress((void**)&Kbp, g_Kb);
    cudaGetSymbolAddress((void**)&Vbp, g_Vb);
    cudaGetSymbolAddress((void**)&kvTp, g_kvT);
    cudaGetSymbolAddress((void**)&kvp, g_kvp);
    cudaGetSymbolAddress((void**)&zp,  g_zp);
    cudaGetSymbolAddress((void**)&zb,  g_z);

    cudaFuncSetAttribute(gemm_qkv, cudaFuncAttributeMaxDynamicSharedMemorySize, SMEM_BYTES);
    cudaFuncSetAttribute(gemm_out, cudaFuncAttributeMaxDynamicSharedMemorySize, SMEM_BYTES);
    cudaFuncSetAttribute(kv_hmma,   cudaFuncAttributeMaxDynamicSharedMemorySize, KV_SMEM);
    cudaFuncSetAttribute(attn_hmma, cudaFuncAttributeMaxDynamicSharedMemorySize, AT_SMEM);

    const int WSZ = DMODEL * DMODEL;
    const int XN8 = ROWS * DMODEL / 8;
    const int WN8 = WSZ / 8;

    dim3 gb(GTHREADS);

    // weights -> blocked fp16, one launch (z = 4 tensors)
    cvt_swz_multi<<<dim3(512, 1, 4), 256>>>(wq, wk, wv, wo, Wbp, (size_t)WSZ, WN8);
    // activations -> blocked fp16, one launch (z = 3 tensors)
    cvt_swz_multi<<<dim3(2048, 1, 3), 256>>>(queries, keys, values, nullptr,
                                             Xbp, ASTRIDE, XN8);

    // merged QKV projections (3072 CTAs, wave-packed)
    gemm_qkv<<<dim3(DMODEL / BN, ROWS / BM, 3), gb, SMEM_BYTES>>>(
        Xbp, Wbp, bq, bk, bv, Qbp, Kbp, Vbp);

    kv_hmma  <<<BATCH * HEADS * KSPLIT, 256, KV_SMEM>>>(Kbp, Vbp, kvp, zp);
    kv_reduce<<<BATCH * HEADS, 256>>>(kvp, zp, kvTp, zb);
    attn_hmma<<<dim3(ROWS / 128, 2), 256, AT_SMEM>>>(Qbp, kvTp, zb, Abp);

    // output projection (fp32 out)
    gemm_out<<<dim3(DMODEL / BN, ROWS / BM), gb, SMEM_BYTES>>>(
        Abp, Wbp + 3 * WSZ, bo, out);
}

// round 14
// speedup vs baseline: 1.1634x; 1.0099x over previous
#include <cuda_runtime.h>
#include <cuda_fp16.h>
#include <cstdint>

// Problem constants (fixed by reference)
#define DMODEL 1024
#define HEADS  16
#define DH     64
#define BATCH  4
#define SEQ    4096
#define ROWS   (BATCH * SEQ)   // 16384
#define KSPLIT 8
#define EPSV   1e-6f

// GEMM tiling (HMMA mma.sync; tcgen05 unavailable on compute_103 virtual arch)
#define BM 128
#define BN 128
#define NCH (DMODEL / 64)       // 16 chunks of 64 fp16 per 1024-row
#define GTHREADS 256
#define STAGES 3                // 99KB smem -> 2 CTAs/SM

// Blocked-swizzled fp16 layout: 16KB block per (row-tile of 128, 64-col chunk).
#define BLK_BYTES 16384

#define A_PL 0
#define B_PL 16384
#define STAGE 32768
#define SMEM_BYTES (1024 + STAGES * STAGE)   // 99328

#define KV_STAGE 32768                        // K 16KB + V 16KB
#define KV_SMEM  (1024 + 2 * KV_STAGE)        // 66560
#define AT_STAGE 24576                        // Q 16KB + kvT 8KB
#define AT_SMEM  (1024 + 2 * AT_STAGE)        // 50176

#define ASTRIDE ((size_t)ROWS * DMODEL)

// ---------------- scratch (device globals; no allocation allowed) ------------
__device__ __half g_Xb[3 * ROWS * DMODEL];          // blocked q/k/v inputs
__device__ __half g_Ab[ROWS * DMODEL];              // S (blocked)
__device__ __half g_Wb[4 * DMODEL * DMODEL];        // blocked wq,wk,wv,wo
__device__ __half g_Qb[ROWS * DMODEL];              // Q fp16 blocked
__device__ __half g_Kb[ROWS * DMODEL];              // K fp16 blocked
__device__ __half g_Vb[ROWS * DMODEL];              // V fp16 blocked
__device__ float g_kvp[BATCH * HEADS * KSPLIT * DH * DH];
__device__ float g_zp [BATCH * HEADS * KSPLIT * DH];
__device__ __half g_kvT[BATCH * HEADS * DH * DH];   // kv^T fp16 swizzled [e][d]
__device__ float g_z  [BATCH * HEADS * DH];

// =============================== helpers ====================================
__device__ __forceinline__ uint32_t smem_u32(const void* p) {
    uint32_t a;
    asm("{ .reg .u64 t; cvta.to.shared.u64 t, %1; cvt.u32.u64 %0, t; }"
        : "=r"(a) : "l"(p));
    return a;
}
__device__ __forceinline__ void ldsm4(uint32_t& r0, uint32_t& r1, uint32_t& r2,
                                      uint32_t& r3, uint32_t addr) {
    asm volatile("ldmatrix.sync.aligned.m8n8.x4.shared.b16 {%0,%1,%2,%3}, [%4];"
                 : "=r"(r0), "=r"(r1), "=r"(r2), "=r"(r3) : "r"(addr));
}
__device__ __forceinline__ void ldsm4t(uint32_t& r0, uint32_t& r1, uint32_t& r2,
                                       uint32_t& r3, uint32_t addr) {
    asm volatile("ldmatrix.sync.aligned.m8n8.x4.trans.shared.b16 {%0,%1,%2,%3}, [%4];"
                 : "=r"(r0), "=r"(r1), "=r"(r2), "=r"(r3) : "r"(addr));
}
__device__ __forceinline__ void mma_fp16(float* c, const uint32_t* a, const uint32_t* b) {
    asm volatile(
        "mma.sync.aligned.m16n8k16.row.col.f32.f16.f16.f32 "
        "{%0,%1,%2,%3}, {%4,%5,%6,%7}, {%8,%9}, {%0,%1,%2,%3};"
        : "+f"(c[0]), "+f"(c[1]), "+f"(c[2]), "+f"(c[3])
        : "r"(a[0]), "r"(a[1]), "r"(a[2]), "r"(a[3]), "r"(b[0]), "r"(b[1]));
}
__device__ __forceinline__ void mbar_init(uint32_t addr, uint32_t cnt) {
    asm volatile("mbarrier.init.shared.b64 [%0], %1;" :: "r"(addr), "r"(cnt) : "memory");
}
__device__ __forceinline__ void mbar_expect_tx(uint32_t addr, uint32_t bytes) {
    asm volatile("mbarrier.arrive.expect_tx.shared.b64 _, [%0], %1;"
                 :: "r"(addr), "r"(bytes) : "memory");
}
__device__ __forceinline__ void mbar_wait(uint32_t addr, uint32_t parity) {
    asm volatile(
        "{\n\t.reg .pred P;\n"
        "W%=:\n\t"
        "mbarrier.try_wait.parity.acquire.cta.shared::cta.b64 P, [%0], %1, 0x989680;\n\t"
        "@!P bra W%=;\n\t"
        "}"
        :: "r"(addr), "r"(parity) : "memory");
}
__device__ __forceinline__ void bulk_cp(uint32_t sdst, const void* gsrc,
                                        uint32_t bytes, uint32_t mbar) {
    asm volatile(
        "cp.async.bulk.shared::cta.global.mbarrier::complete_tx::bytes [%0], [%1], %2, [%3];"
        :: "r"(sdst), "l"(gsrc), "r"(bytes), "r"(mbar) : "memory");
}
__device__ __forceinline__ uint2 cvt_f16x4(float4 v) {
    __half2 p01 = __floats2half2_rn(v.x, v.y);
    __half2 p23 = __floats2half2_rn(v.z, v.w);
    return make_uint2(*(uint32_t*)&p01, *(uint32_t*)&p23);
}
__device__ __forceinline__ float h2sum(uint32_t r) {
    float2 f = __half22float2(*(__half2*)&r);
    return f.x + f.y;
}

// =============================================================================
// fp32 [rows][1024] -> blocked-swizzled fp16; up to 4 tensors per launch (z).
// Each thread handles 8 floats -> ONE 16B store (16B = swizzle atom, aligned).
// =============================================================================
__global__ __launch_bounds__(256)
void cvt_swz_multi(const float* __restrict__ s0, const float* __restrict__ s1,
                   const float* __restrict__ s2, const float* __restrict__ s3,
                   __half* __restrict__ dst, size_t dstride, int n8) {
    const float* src = (blockIdx.z == 0) ? s0 : (blockIdx.z == 1) ? s1
                     : (blockIdx.z == 2) ? s2 : s3;
    __half* d = dst + (size_t)blockIdx.z * dstride;
    for (int i = blockIdx.x * 256 + threadIdx.x; i < n8; i += gridDim.x * 256) {
        const int grow = i >> 7;
        const int gcol = (i & 127) * 8;
        const int blk  = grow >> 7;
        const int r    = grow & 127;
        const int c    = gcol >> 6;
        const uint32_t colb = (uint32_t)((gcol & 63) * 2);
        const size_t off = ((size_t)(blk * NCH + c) << 14)
                         + (uint32_t)(r * 128) + (colb ^ ((uint32_t)(r & 7) << 4));
        float4 va = ((const float4*)src)[2 * i];
        float4 vb = ((const float4*)src)[2 * i + 1];
        uint2 pa = cvt_f16x4(va);
        uint2 pb = cvt_f16x4(vb);
        *(uint4*)((char*)d + off) = make_uint4(pa.x, pa.y, pb.x, pb.y);
    }
}

// =============================================================================
// Merged QKV projection GEMM (NT): grid.z selects {input, weight, bias, out, phi}.
// CTA 128x128, 256 threads, 3 stages -> 2 CTAs/SM.
// =============================================================================
__global__ __launch_bounds__(GTHREADS, 2)
void gemm_qkv(const __half* __restrict__ Xb, const __half* __restrict__ Wb,
              const float* __restrict__ bq, const float* __restrict__ bk,
              const float* __restrict__ bv,
              __half* __restrict__ Qb, __half* __restrict__ Kb,
              __half* __restrict__ Vb) {
    extern __shared__ char sm[];
    const uint32_t sbase = smem_u32(sm);
    const int tid = threadIdx.x;
    const int lane = tid & 31;
    const int wid = tid >> 5;
    const int wm = wid & 3;
    const int wn = wid >> 2;
    const int bm = blockIdx.y;
    const int bn = blockIdx.x;
    const int zi = blockIdx.z;

    const __half* Ab = Xb + (size_t)zi * ASTRIDE;
    const __half* Bb = Wb + (size_t)zi * (DMODEL * DMODEL);
    const float* bias = (zi == 0) ? bq : (zi == 1) ? bk : bv;
    __half* Yh = (zi == 0) ? Qb : (zi == 1) ? Kb : Vb;
    const bool phi = (zi != 2);

    if (tid == 0) {
        #pragma unroll
        for (int s = 0; s < STAGES; s++) mbar_init(sbase + s * 8, 1);
    }
    __syncthreads();

    const char* gAb = (const char*)Ab + ((size_t)(bm * NCH) << 14);
    const char* gBb = (const char*)Bb + ((size_t)(bn * NCH) << 14);

    int row_a[2];
    row_a[0] = wm * 32 + (lane & 15);
    row_a[1] = row_a[0] + 16;
    const uint32_t a_colb = (uint32_t)((lane >> 4) << 4);
    uint32_t a_base[2], a_mask[2];
    #pragma unroll
    for (int mt = 0; mt < 2; mt++) {
        a_base[mt] = (uint32_t)(row_a[mt] * 128);
        a_mask[mt] = (uint32_t)((row_a[mt] & 7) << 4);
    }
    int nrow[4];
    #pragma unroll
    for (int ntp = 0; ntp < 4; ntp++)
        nrow[ntp] = wn * 64 + ntp * 16 + (lane & 7) + ((lane >> 4) << 3);
    const uint32_t b_colb = (lane & 8) ? 16u : 0u;
    uint32_t b_base[4], b_mask[4];
    #pragma unroll
    for (int ntp = 0; ntp < 4; ntp++) {
        b_base[ntp] = (uint32_t)(nrow[ntp] * 128);
        b_mask[ntp] = (uint32_t)((nrow[ntp] & 7) << 4);
    }

    float acc[2][8][4];
    #pragma unroll
    for (int mt = 0; mt < 2; mt++)
        #pragma unroll
        for (int nt = 0; nt < 8; nt++)
            #pragma unroll
            for (int i = 0; i < 4; i++) acc[mt][nt][i] = 0.f;

    auto issue = [&](int c) {
        const int s = c % STAGES;
        const uint32_t mb = sbase + s * 8;
        const uint32_t st = sbase + 1024 + s * STAGE;
        mbar_expect_tx(mb, 2 * BLK_BYTES);
        bulk_cp(st + A_PL, gAb + ((size_t)c << 14), BLK_BYTES, mb);
        bulk_cp(st + B_PL, gBb + ((size_t)c << 14), BLK_BYTES, mb);
    };

    if (tid == 0) { issue(0); issue(1); }

    for (int c = 0; c < NCH; c++) {
        mbar_wait(sbase + (c % STAGES) * 8, (c / STAGES) & 1);
        if (tid == 0 && c + 2 < NCH) issue(c + 2);

        const uint32_t stg = sbase + 1024 + (uint32_t)((c % STAGES) * STAGE);
        #pragma unroll
        for (int ks = 0; ks < 4; ks++) {
            const uint32_t kb = (uint32_t)(ks * 32);
            uint32_t Ar[2][4];
            #pragma unroll
            for (int mt = 0; mt < 2; mt++) {
                uint32_t off = a_base[mt] + ((kb + a_colb) ^ a_mask[mt]);
                ldsm4(Ar[mt][0], Ar[mt][1], Ar[mt][2], Ar[mt][3], stg + A_PL + off);
            }
            uint32_t Br[8][2];
            #pragma unroll
            for (int ntp = 0; ntp < 4; ntp++) {
                uint32_t off = b_base[ntp] + ((kb + b_colb) ^ b_mask[ntp]);
                ldsm4(Br[2 * ntp][0], Br[2 * ntp][1], Br[2 * ntp + 1][0], Br[2 * ntp + 1][1],
                      stg + B_PL + off);
            }
            #pragma unroll
            for (int mt = 0; mt < 2; mt++)
                #pragma unroll
                for (int nt = 0; nt < 8; nt++)
                    mma_fp16(acc[mt][nt], Ar[mt], Br[nt]);
        }
        __syncthreads();
    }

    // ---- epilogue: bias (+ phi), store fp16 blocked ----
    const int lr = lane >> 2;
    const int lc = lane & 3;
    #pragma unroll
    for (int mt = 0; mt < 2; mt++) {
        const int r0l = wm * 32 + mt * 16 + lr;
        #pragma unroll
        for (int nt = 0; nt < 8; nt++) {
            const int gc = bn * BN + wn * 64 + nt * 8 + lc * 2;
            const float b0 = __ldg(&bias[gc]);
            const float b1 = __ldg(&bias[gc + 1]);
            float o00 = acc[mt][nt][0] + b0;
            float o01 = acc[mt][nt][1] + b1;
            float o10 = acc[mt][nt][2] + b0;
            float o11 = acc[mt][nt][3] + b1;
            if (phi) {
                o00 = (o00 > 0.f) ? (o00 + 1.f) : __expf(o00);
                o01 = (o01 > 0.f) ? (o01 + 1.f) : __expf(o01);
                o10 = (o10 > 0.f) ? (o10 + 1.f) : __expf(o10);
                o11 = (o11 > 0.f) ? (o11 + 1.f) : __expf(o11);
            }
            const int cch = gc >> 6;
            const uint32_t colb = (uint32_t)((gc & 63) * 2);
            const size_t blkb = ((size_t)(bm * NCH + cch)) << 14;
            __half2 p0 = __floats2half2_rn(o00, o01);
            __half2 p1 = __floats2half2_rn(o10, o11);
            const uint32_t ra = (uint32_t)r0l, rb = (uint32_t)(r0l + 8);
            *(uint32_t*)((char*)Yh + blkb + ra * 128 + (colb ^ ((ra & 7) << 4))) =
                *(uint32_t*)&p0;
            *(uint32_t*)((char*)Yh + blkb + rb * 128 + (colb ^ ((rb & 7) << 4))) =
                *(uint32_t*)&p1;
        }
    }
}

// =============================================================================
// Output projection GEMM (fp32 row-major out), same engine.
// =============================================================================
__global__ __launch_bounds__(GTHREADS, 2)
void gemm_out(const __half* __restrict__ Ab, const __half* __restrict__ Bb,
              const float* __restrict__ bias, float* __restrict__ Y) {
    extern __shared__ char sm[];
    const uint32_t sbase = smem_u32(sm);
    const int tid = threadIdx.x;
    const int lane = tid & 31;
    const int wid = tid >> 5;
    const int wm = wid & 3;
    const int wn = wid >> 2;
    const int bm = blockIdx.y;
    const int bn = blockIdx.x;

    if (tid == 0) {
        #pragma unroll
        for (int s = 0; s < STAGES; s++) mbar_init(sbase + s * 8, 1);
    }
    __syncthreads();

    const char* gAb = (const char*)Ab + ((size_t)(bm * NCH) << 14);
    const char* gBb = (const char*)Bb + ((size_t)(bn * NCH) << 14);

    int row_a[2];
    row_a[0] = wm * 32 + (lane & 15);
    row_a[1] = row_a[0] + 16;
    const uint32_t a_colb = (uint32_t)((lane >> 4) << 4);
    uint32_t a_base[2], a_mask[2];
    #pragma unroll
    for (int mt = 0; mt < 2; mt++) {
        a_base[mt] = (uint32_t)(row_a[mt] * 128);
        a_mask[mt] = (uint32_t)((row_a[mt] & 7) << 4);
    }
    int nrow[4];
    #pragma unroll
    for (int ntp = 0; ntp < 4; ntp++)
        nrow[ntp] = wn * 64 + ntp * 16 + (lane & 7) + ((lane >> 4) << 3);
    const uint32_t b_colb = (lane & 8) ? 16u : 0u;
    uint32_t b_base[4], b_mask[4];
    #pragma unroll
    for (int ntp = 0; ntp < 4; ntp++) {
        b_base[ntp] = (uint32_t)(nrow[ntp] * 128);
        b_mask[ntp] = (uint32_t)((nrow[ntp] & 7) << 4);
    }

    float acc[2][8][4];
    #pragma unroll
    for (int mt = 0; mt < 2; mt++)
        #pragma unroll
        for (int nt = 0; nt < 8; nt++)
            #pragma unroll
            for (int i = 0; i < 4; i++) acc[mt][nt][i] = 0.f;

    auto issue = [&](int c) {
        const int s = c % STAGES;
        const uint32_t mb = sbase + s * 8;
        const uint32_t st = sbase + 1024 + s * STAGE;
        mbar_expect_tx(mb, 2 * BLK_BYTES);
        bulk_cp(st + A_PL, gAb + ((size_t)c << 14), BLK_BYTES, mb);
        bulk_cp(st + B_PL, gBb + ((size_t)c << 14), BLK_BYTES, mb);
    };

    if (tid == 0) { issue(0); issue(1); }

    for (int c = 0; c < NCH; c++) {
        mbar_wait(sbase + (c % STAGES) * 8, (c / STAGES) & 1);
        if (tid == 0 && c + 2 < NCH) issue(c + 2);

        const uint32_t stg = sbase + 1024 + (uint32_t)((c % STAGES) * STAGE);
        #pragma unroll
        for (int ks = 0; ks < 4; ks++) {
            const uint32_t kb = (uint32_t)(ks * 32);
            uint32_t Ar[2][4];
            #pragma unroll
            for (int mt = 0; mt < 2; mt++) {
                uint32_t off = a_base[mt] + ((kb + a_colb) ^ a_mask[mt]);
                ldsm4(Ar[mt][0], Ar[mt][1], Ar[mt][2], Ar[mt][3], stg + A_PL + off);
            }
            uint32_t Br[8][2];
            #pragma unroll
            for (int ntp = 0; ntp < 4; ntp++) {
                uint32_t off = b_base[ntp] + ((kb + b_colb) ^ b_mask[ntp]);
                ldsm4(Br[2 * ntp][0], Br[2 * ntp][1], Br[2 * ntp + 1][0], Br[2 * ntp + 1][1],
                      stg + B_PL + off);
            }
            #pragma unroll
            for (int mt = 0; mt < 2; mt++)
                #pragma unroll
                for (int nt = 0; nt < 8; nt++)
                    mma_fp16(acc[mt][nt], Ar[mt], Br[nt]);
        }
        __syncthreads();
    }

    const int lr = lane >> 2;
    const int lc = lane & 3;
    #pragma unroll
    for (int mt = 0; mt < 2; mt++) {
        const int gr0 = bm * BM + wm * 32 + mt * 16 + lr;
        #pragma unroll
        for (int nt = 0; nt < 8; nt++) {
            const int gc = bn * BN + wn * 64 + nt * 8 + lc * 2;
            const float b0 = __ldg(&bias[gc]);
            const float b1 = __ldg(&bias[gc + 1]);
            *(float2*)(Y + (size_t)gr0 * DMODEL + gc) =
                make_float2(acc[mt][nt][0] + b0, acc[mt][nt][1] + b1);
            *(float2*)(Y + (size_t)(gr0 + 8) * DMODEL + gc) =
                make_float2(acc[mt][nt][2] + b0, acc[mt][nt][3] + b1);
        }
    }
}

// =============================================================================
// kv partial via HMMA, 256 threads / 8 warps (e-split), KSPLIT=8:
// 4 chunks of 128 m-rows per CTA, depth-2 prefetch (latency amortized).
// warp w: d-range = (w&3)*16, e-half = (w>>2)*32.
// =============================================================================
__global__ __launch_bounds__(256, 1)
void kv_hmma(const __half* __restrict__ Kb, const __half* __restrict__ Vb,
             float* __restrict__ kvp, float* __restrict__ zp) {
    extern __shared__ char sm[];
    const uint32_t sbase = smem_u32(sm);
    const int tid = threadIdx.x;
    const int lane = tid & 31;
    const int wid = tid >> 5;

    const int s  = blockIdx.x % KSPLIT;
    const int bh = blockIdx.x / KSPLIT;
    const int b = bh / HEADS, h = bh % HEADS;
    const int blkbase = b * (SEQ / 128) + s * 4;

    if (tid == 0) { mbar_init(sbase, 1); mbar_init(sbase + 8, 1); }
    __syncthreads();

    auto issue = [&](int j) {
        const int st = j & 1;
        const uint32_t mb = sbase + st * 8;
        const uint32_t dst = sbase + 1024 + st * KV_STAGE;
        mbar_expect_tx(mb, 2 * BLK_BYTES);
        const size_t off = ((size_t)((blkbase + j) * NCH + h)) << 14;
        bulk_cp(dst,         (const char*)Kb + off, BLK_BYTES, mb);
        bulk_cp(dst + 16384, (const char*)Vb + off, BLK_BYTES, mb);
    };
    if (tid == 0) { issue(0); issue(1); }

    const int d0 = (wid & 3) * 16;
    const int eh = wid >> 2;              // 0 or 1: e-half
    const int a_rloc = (lane & 7) + ((lane >> 4) << 3);
    const uint32_t a_cb = (uint32_t)(d0 * 2) + (uint32_t)(((lane >> 3) & 1) << 4);
    const uint32_t a_off = (uint32_t)(a_rloc * 128) + (a_cb ^ ((uint32_t)(a_rloc & 7) << 4));
    const int b_rloc = (lane & 7) + (((lane >> 3) & 1) << 3);
    const uint32_t b_cb0 = (uint32_t)((lane >> 4) << 4);
    uint32_t b_off[2];
    #pragma unroll
    for (int e4 = 0; e4 < 2; e4++)
        b_off[e4] = (uint32_t)(b_rloc * 128)
                  + (((uint32_t)((eh * 2 + e4) * 32) + b_cb0) ^ ((uint32_t)(b_rloc & 7) << 4));

    float acc[4][4];
    #pragma unroll
    for (int nt = 0; nt < 4; nt++)
        #pragma unroll
        for (int i = 0; i < 4; i++) acc[nt][i] = 0.f;
    float zs0 = 0.f, zs1 = 0.f;

    for (int j = 0; j < 4; j++) {
        mbar_wait(sbase + (j & 1) * 8, (j >> 1) & 1);
        const uint32_t bK = sbase + 1024 + (j & 1) * KV_STAGE;
        const uint32_t bV = bK + 16384;
        #pragma unroll
        for (int ks = 0; ks < 8; ks++) {
            uint32_t Ar[4];
            ldsm4t(Ar[0], Ar[1], Ar[2], Ar[3], bK + (uint32_t)(ks * 2048) + a_off);
            uint32_t Br[4][2];
            #pragma unroll
            for (int e4 = 0; e4 < 2; e4++) {
                uint32_t r0, r1, r2, r3;
                ldsm4t(r0, r1, r2, r3, bV + (uint32_t)(ks * 2048) + b_off[e4]);
                Br[2 * e4][0] = r0; Br[2 * e4][1] = r1;
                Br[2 * e4 + 1][0] = r2; Br[2 * e4 + 1][1] = r3;
            }
            #pragma unroll
            for (int nt = 0; nt < 4; nt++) mma_fp16(acc[nt], Ar, Br[nt]);
            if (eh == 0) {
                zs0 += h2sum(Ar[0]) + h2sum(Ar[2]);
                zs1 += h2sum(Ar[1]) + h2sum(Ar[3]);
            }
        }
        __syncthreads();
        if (tid == 0 && j + 2 < 4) issue(j + 2);
    }

    const int g = lane >> 2;
    const int ec = 2 * (lane & 3);
    float* kout = kvp + (size_t)blockIdx.x * (DH * DH);
    #pragma unroll
    for (int nt = 0; nt < 4; nt++) {
        const int e = eh * 32 + nt * 8 + ec;
        *(float2*)&kout[(d0 + g) * DH + e]     = make_float2(acc[nt][0], acc[nt][1]);
        *(float2*)&kout[(d0 + g + 8) * DH + e] = make_float2(acc[nt][2], acc[nt][3]);
    }
    if (eh == 0) {
        zs0 += __shfl_xor_sync(0xFFFFFFFF, zs0, 1);
        zs0 += __shfl_xor_sync(0xFFFFFFFF, zs0, 2);
        zs1 += __shfl_xor_sync(0xFFFFFFFF, zs1, 1);
        zs1 += __shfl_xor_sync(0xFFFFFFFF, zs1, 2);
        if ((lane & 3) == 0) {
            zp[(size_t)blockIdx.x * DH + d0 + g]     = zs0;
            zp[(size_t)blockIdx.x * DH + d0 + g + 8] = zs1;
        }
    }
}

// =============================================================================
// reduce partials -> kvT fp16 swizzled [e][d] + z fp32
// =============================================================================
__global__ __launch_bounds__(256)
void kv_reduce(const float* __restrict__ kvp, const float* __restrict__ zp,
               __half* __restrict__ kvT, float* __restrict__ zo) {
    const int bh = blockIdx.x;
    const int tid = threadIdx.x;
    for (int i = tid; i < DH * DH; i += 256) {
        float sum = 0.f;
        #pragma unroll
        for (int s = 0; s < KSPLIT; s++)
            sum += kvp[((size_t)bh * KSPLIT + s) * (DH * DH) + i];
        const int d = i >> 6, e = i & 63;
        const size_t off = (size_t)bh * 8192 + (uint32_t)(e * 128)
                         + (((uint32_t)(d * 2)) ^ ((uint32_t)(e & 7) << 4));
        *(__half*)((char*)kvT + off) = __float2half_rn(sum);
    }
    if (tid < DH) {
        float sum = 0.f;
        #pragma unroll
        for (int s = 0; s < KSPLIT; s++)
            sum += zp[((size_t)bh * KSPLIT + s) * DH + tid];
        zo[(size_t)bh * DH + tid] = sum;
    }
}

// =============================================================================
// attn via HMMA: out[n][e] = (sum_d Q[n][d] kvT[e][d]) / (q.z + eps).
// grid = (ROWS/128, 2); occupancy 2 (smem 50KB x 2 fits).
// =============================================================================
__global__ __launch_bounds__(256, 2)
void attn_hmma(const __half* __restrict__ Qb, const __half* __restrict__ kvT,
               const float* __restrict__ z, __half* __restrict__ Sb) {
    extern __shared__ char sm[];
    __shared__ float zsm[2][64];
    const uint32_t sbase = smem_u32(sm);
    const int tid = threadIdx.x;
    const int lane = tid & 31;
    const int wid = tid >> 5;
    const int blk = blockIdx.x;
    const int h0 = blockIdx.y * 8;
    const int b = blk >> 5;

    if (tid == 0) { mbar_init(sbase, 1); mbar_init(sbase + 8, 1); }

    auto issue = [&](int hh) {
        const int h = h0 + hh;
        const int st = hh & 1;
        const uint32_t mb = sbase + st * 8;
        const uint32_t dst = sbase + 1024 + st * AT_STAGE;
        mbar_expect_tx(mb, 16384 + 8192);
        bulk_cp(dst, (const char*)Qb + (((size_t)(blk * NCH + h)) << 14), 16384, mb);
        bulk_cp(dst + 16384, (const char*)kvT + (((size_t)(b * HEADS + h)) << 13), 8192, mb);
    };
    __syncthreads();
    if (tid == 0) { issue(0); issue(1); }
    if (tid < 64) {
        zsm[0][tid] = z[(size_t)(b * HEADS + h0 + 0) * DH + tid];
        zsm[1][tid] = z[(size_t)(b * HEADS + h0 + 1) * DH + tid];
    }
    __syncthreads();

    const int row_a = wid * 16 + (lane & 15);
    const uint32_t a_base = (uint32_t)(row_a * 128);
    const uint32_t a_mask = (uint32_t)((row_a & 7) << 4);
    const uint32_t a_colb = (uint32_t)((lane >> 4) << 4);
    int nrow[4];
    #pragma unroll
    for (int ntp = 0; ntp < 4; ntp++)
        nrow[ntp] = ntp * 16 + (lane & 7) + ((lane >> 4) << 3);
    const uint32_t b_colb = (lane & 8) ? 16u : 0u;
    uint32_t b_base[4], b_mask[4];
    #pragma unroll
    for (int ntp = 0; ntp < 4; ntp++) {
        b_base[ntp] = (uint32_t)(nrow[ntp] * 128);
        b_mask[ntp] = (uint32_t)((nrow[ntp] & 7) << 4);
    }

    const int g = lane >> 2;
    const int ec = 2 * (lane & 3);

    for (int hh = 0; hh < 8; hh++) {
        const int h = h0 + hh;
        const int st = hh & 1;
        mbar_wait(sbase + st * 8, (hh >> 1) & 1);
        const uint32_t bQ = sbase + 1024 + st * AT_STAGE;
        const uint32_t bKV = bQ + 16384;

        float acc[8][4];
        #pragma unroll
        for (int nt = 0; nt < 8; nt++)
            #pragma unroll
            for (int i = 0; i < 4; i++) acc[nt][i] = 0.f;
        float den0 = 0.f, den1 = 0.f;

        #pragma unroll
        for (int ks = 0; ks < 4; ks++) {
            const uint32_t kb = (uint32_t)(ks * 32);
            uint32_t Ar[4];
            ldsm4(Ar[0], Ar[1], Ar[2], Ar[3], bQ + a_base + ((kb + a_colb) ^ a_mask));
            uint32_t Br[8][2];
            #pragma unroll
            for (int ntp = 0; ntp < 4; ntp++) {
                uint32_t off = b_base[ntp] + ((kb + b_colb) ^ b_mask[ntp]);
                ldsm4(Br[2 * ntp][0], Br[2 * ntp][1], Br[2 * ntp + 1][0], Br[2 * ntp + 1][1],
                      bKV + off);
            }
            #pragma unroll
            for (int nt = 0; nt < 8; nt++) mma_fp16(acc[nt], Ar, Br[nt]);

            const int dbase = ks * 16 + ec;
            const float z0 = zsm[st][dbase],     z1 = zsm[st][dbase + 1];
            const float z8 = zsm[st][dbase + 8], z9 = zsm[st][dbase + 9];
            float2 a0 = __half22float2(*(__half2*)&Ar[0]);
            float2 a1 = __half22float2(*(__half2*)&Ar[1]);
            float2 a2 = __half22float2(*(__half2*)&Ar[2]);
            float2 a3 = __half22float2(*(__half2*)&Ar[3]);
            den0 += a0.x * z0 + a0.y * z1 + a2.x * z8 + a2.y * z9;
            den1 += a1.x * z0 + a1.y * z1 + a3.x * z8 + a3.y * z9;
        }
        den0 += __shfl_xor_sync(0xFFFFFFFF, den0, 1);
        den0 += __shfl_xor_sync(0xFFFFFFFF, den0, 2);
        den1 += __shfl_xor_sync(0xFFFFFFFF, den1, 1);
        den1 += __shfl_xor_sync(0xFFFFFFFF, den1, 2);
        const float rinv0 = 1.0f / (den0 + EPSV);
        const float rinv1 = 1.0f / (den1 + EPSV);

        const size_t blkb = ((size_t)(blk * NCH + h)) << 14;
        const uint32_t ra = (uint32_t)(wid * 16 + g);
        const uint32_t rb = ra + 8;
        #pragma unroll
        for (int nt = 0; nt < 8; nt++) {
            const uint32_t colb = (uint32_t)((nt * 8 + ec) * 2);
            __half2 p0 = __floats2half2_rn(acc[nt][0] * rinv0, acc[nt][1] * rinv0);
            __half2 p1 = __floats2half2_rn(acc[nt][2] * rinv1, acc[nt][3] * rinv1);
            *(uint32_t*)((char*)Sb + blkb + ra * 128 + (colb ^ ((ra & 7) << 4))) =
                *(uint32_t*)&p0;
            *(uint32_t*)((char*)Sb + blkb + rb * 128 + (colb ^ ((rb & 7) << 4))) =
                *(uint32_t*)&p1;
        }
        __syncthreads();
        if (tid == 0 && hh + 2 < 8) issue(hh + 2);
        if (tid < 64 && hh + 2 < 8)
            zsm[st][tid] = z[(size_t)(b * HEADS + h0 + hh + 2) * DH + tid];
    }
}

// =============================================================================
extern "C" void kernel_launch(void* const* d_in, const int* in_sizes, int n_in,
                              void* d_out, int out_size) {
    const float* queries = (const float*)d_in[0];
    const float* keys    = (const float*)d_in[1];
    const float* values  = (const float*)d_in[2];
    const float* wq = (const float*)d_in[3];
    const float* bq = (const float*)d_in[4];
    const float* wk = (const float*)d_in[5];
    const float* bk = (const float*)d_in[6];
    const float* wv = (const float*)d_in[7];
    const float* bv = (const float*)d_in[8];
    const float* wo = (const float*)d_in[9];
    const float* bo = (const float*)d_in[10];
    float* out = (float*)d_out;

    __half *Xbp, *Abp, *Wbp, *Qbp, *Kbp, *Vbp, *kvTp;
    float *kvp, *zp, *zb;
    cudaGetSymbolAddress((void**)&Xbp, g_Xb);
    cudaGetSymbolAddress((void**)&Abp, g_Ab);
    cudaGetSymbolAddress((void**)&Wbp, g_Wb);
    cudaGetSymbolAddress((void**)&Qbp, g_Qb);
    cudaGetSymbolAddress((void**)&Kbp, g_Kb);
    cudaGetSymbolAddress((void**)&Vbp, g_Vb);
    cudaGetSymbolAddress((void**)&kvTp, g_kvT);
    cudaGetSymbolAddress((void**)&kvp, g_kvp);
    cudaGetSymbolAddress((void**)&zp,  g_zp);
    cudaGetSymbolAddress((void**)&zb,  g_z);

    cudaFuncSetAttribute(gemm_qkv, cudaFuncAttributeMaxDynamicSharedMemorySize, SMEM_BYTES);
    cudaFuncSetAttribute(gemm_out, cudaFuncAttributeMaxDynamicSharedMemorySize, SMEM_BYTES);
    cudaFuncSetAttribute(kv_hmma,   cudaFuncAttributeMaxDynamicSharedMemorySize, KV_SMEM);
    cudaFuncSetAttribute(attn_hmma, cudaFuncAttributeMaxDynamicSharedMemorySize, AT_SMEM);

    const int WSZ = DMODEL * DMODEL;
    const int XN8 = ROWS * DMODEL / 8;
    const int WN8 = WSZ / 8;

    dim3 gb(GTHREADS);

    // weights -> blocked fp16, one launch (z = 4 tensors)
    cvt_swz_multi<<<dim3(512, 1, 4), 256>>>(wq, wk, wv, wo, Wbp, (size_t)WSZ, WN8);
    // activations -> blocked fp16, one launch (z = 3 tensors)
    cvt_swz_multi<<<dim3(4096, 1, 3), 256>>>(queries, keys, values, nullptr,
                                             Xbp, ASTRIDE, XN8);

    // merged QKV projections (3072 CTAs, wave-packed)
    gemm_qkv<<<dim3(DMODEL / BN, ROWS / BM, 3), gb, SMEM_BYTES>>>(
        Xbp, Wbp, bq, bk, bv, Qbp, Kbp, Vbp);

    kv_hmma  <<<BATCH * HEADS * KSPLIT, 256, KV_SMEM>>>(Kbp, Vbp, kvp, zp);
    kv_reduce<<<BATCH * HEADS, 256>>>(kvp, zp, kvTp, zb);
    attn_hmma<<<dim3(ROWS / 128, 2), 256, AT_SMEM>>>(Qbp, kvTp, zb, Abp);

    // output projection (fp32 out)
    gemm_out<<<dim3(DMODEL / BN, ROWS / BM), gb, SMEM_BYTES>>>(
        Abp, Wbp + 3 * WSZ, bo, out);
}

// round 15
// speedup vs baseline: 1.1743x; 1.0094x over previous
#include <cuda_runtime.h>
#include <cuda_fp16.h>
#include <cstdint>

// Problem constants (fixed by reference)
#define DMODEL 1024
#define HEADS  16
#define DH     64
#define BATCH  4
#define SEQ    4096
#define ROWS   (BATCH * SEQ)   // 16384
#define KSPLIT 8
#define EPSV   1e-6f

// GEMM tiling (HMMA mma.sync; tcgen05 unavailable on compute_103 virtual arch)
#define BM 128
#define BN 128
#define NCH (DMODEL / 64)       // 16 chunks of 64 fp16 per 1024-row
#define GTHREADS 256
#define STAGES 3                // 99KB smem -> 2 CTAs/SM

// Blocked-swizzled fp16 layout: 16KB block per (row-tile of 128, 64-col chunk).
#define BLK_BYTES 16384

#define A_PL 0
#define B_PL 16384
#define STAGE 32768
#define SMEM_BYTES (1024 + STAGES * STAGE)   // 99328

#define KV_STAGE 32768                        // K 16KB + V 16KB
#define KV_SMEM  (1024 + 2 * KV_STAGE)        // 66560
#define AT_STAGE 24576                        // Q 16KB + kvT 8KB
#define AT_SMEM  (1024 + 2 * AT_STAGE)        // 50176

#define ASTRIDE ((size_t)ROWS * DMODEL)
#define WSZC    (DMODEL * DMODEL)

// ---------------- scratch (device globals; no allocation allowed) ------------
__device__ __half g_Xb[3 * ROWS * DMODEL];          // blocked q/k/v inputs
__device__ __half g_Ab[ROWS * DMODEL];              // S (blocked)
__device__ __half g_Wb[4 * DMODEL * DMODEL];        // blocked wq,wk,wv,wo
__device__ __half g_Qb[ROWS * DMODEL];              // Q fp16 blocked
__device__ __half g_Kb[ROWS * DMODEL];              // K fp16 blocked
__device__ __half g_Vb[ROWS * DMODEL];              // V fp16 blocked
__device__ float g_kvp[BATCH * HEADS * KSPLIT * DH * DH];
__device__ float g_zp [BATCH * HEADS * KSPLIT * DH];
__device__ __half g_kvT[BATCH * HEADS * DH * DH];   // kv^T fp16 swizzled [e][d]
__device__ float g_z  [BATCH * HEADS * DH];

// =============================== helpers ====================================
__device__ __forceinline__ uint32_t smem_u32(const void* p) {
    uint32_t a;
    asm("{ .reg .u64 t; cvta.to.shared.u64 t, %1; cvt.u32.u64 %0, t; }"
        : "=r"(a) : "l"(p));
    return a;
}
__device__ __forceinline__ void ldsm4(uint32_t& r0, uint32_t& r1, uint32_t& r2,
                                      uint32_t& r3, uint32_t addr) {
    asm volatile("ldmatrix.sync.aligned.m8n8.x4.shared.b16 {%0,%1,%2,%3}, [%4];"
                 : "=r"(r0), "=r"(r1), "=r"(r2), "=r"(r3) : "r"(addr));
}
__device__ __forceinline__ void ldsm4t(uint32_t& r0, uint32_t& r1, uint32_t& r2,
                                       uint32_t& r3, uint32_t addr) {
    asm volatile("ldmatrix.sync.aligned.m8n8.x4.trans.shared.b16 {%0,%1,%2,%3}, [%4];"
                 : "=r"(r0), "=r"(r1), "=r"(r2), "=r"(r3) : "r"(addr));
}
__device__ __forceinline__ void mma_fp16(float* c, const uint32_t* a, const uint32_t* b) {
    asm volatile(
        "mma.sync.aligned.m16n8k16.row.col.f32.f16.f16.f32 "
        "{%0,%1,%2,%3}, {%4,%5,%6,%7}, {%8,%9}, {%0,%1,%2,%3};"
        : "+f"(c[0]), "+f"(c[1]), "+f"(c[2]), "+f"(c[3])
        : "r"(a[0]), "r"(a[1]), "r"(a[2]), "r"(a[3]), "r"(b[0]), "r"(b[1]));
}
__device__ __forceinline__ void mbar_init(uint32_t addr, uint32_t cnt) {
    asm volatile("mbarrier.init.shared.b64 [%0], %1;" :: "r"(addr), "r"(cnt) : "memory");
}
__device__ __forceinline__ void mbar_expect_tx(uint32_t addr, uint32_t bytes) {
    asm volatile("mbarrier.arrive.expect_tx.shared.b64 _, [%0], %1;"
                 :: "r"(addr), "r"(bytes) : "memory");
}
__device__ __forceinline__ void mbar_wait(uint32_t addr, uint32_t parity) {
    asm volatile(
        "{\n\t.reg .pred P;\n"
        "W%=:\n\t"
        "mbarrier.try_wait.parity.acquire.cta.shared::cta.b64 P, [%0], %1, 0x989680;\n\t"
        "@!P bra W%=;\n\t"
        "}"
        :: "r"(addr), "r"(parity) : "memory");
}
__device__ __forceinline__ void bulk_cp(uint32_t sdst, const void* gsrc,
                                        uint32_t bytes, uint32_t mbar) {
    asm volatile(
        "cp.async.bulk.shared::cta.global.mbarrier::complete_tx::bytes [%0], [%1], %2, [%3];"
        :: "r"(sdst), "l"(gsrc), "r"(bytes), "r"(mbar) : "memory");
}
__device__ __forceinline__ uint2 cvt_f16x4(float4 v) {
    __half2 p01 = __floats2half2_rn(v.x, v.y);
    __half2 p23 = __floats2half2_rn(v.z, v.w);
    return make_uint2(*(uint32_t*)&p01, *(uint32_t*)&p23);
}
__device__ __forceinline__ float h2sum(uint32_t r) {
    float2 f = __half22float2(*(__half2*)&r);
    return f.x + f.y;
}

// =============================================================================
// Merged conversion: z = 0..3 -> weights, z = 4..6 -> activations.
// fp32 [rows][1024] -> blocked-swizzled fp16; 8 floats -> one 16B store.
// =============================================================================
__global__ __launch_bounds__(256)
void cvt_all(const float* __restrict__ w0, const float* __restrict__ w1,
             const float* __restrict__ w2, const float* __restrict__ w3,
             const float* __restrict__ a0, const float* __restrict__ a1,
             const float* __restrict__ a2,
             __half* __restrict__ Wb, __half* __restrict__ Xb,
             int wn8, int an8) {
    const int zi = blockIdx.z;
    const float* src;
    __half* d;
    int n8;
    if (zi < 4) {
        src = (zi == 0) ? w0 : (zi == 1) ? w1 : (zi == 2) ? w2 : w3;
        d = Wb + (size_t)zi * WSZC;
        n8 = wn8;
    } else {
        src = (zi == 4) ? a0 : (zi == 5) ? a1 : a2;
        d = Xb + (size_t)(zi - 4) * ASTRIDE;
        n8 = an8;
    }
    for (int i = blockIdx.x * 256 + threadIdx.x; i < n8; i += gridDim.x * 256) {
        const int grow = i >> 7;
        const int gcol = (i & 127) * 8;
        const int blk  = grow >> 7;
        const int r    = grow & 127;
        const int c    = gcol >> 6;
        const uint32_t colb = (uint32_t)((gcol & 63) * 2);
        const size_t off = ((size_t)(blk * NCH + c) << 14)
                         + (uint32_t)(r * 128) + (colb ^ ((uint32_t)(r & 7) << 4));
        float4 va = ((const float4*)src)[2 * i];
        float4 vb = ((const float4*)src)[2 * i + 1];
        uint2 pa = cvt_f16x4(va);
        uint2 pb = cvt_f16x4(vb);
        *(uint4*)((char*)d + off) = make_uint4(pa.x, pa.y, pb.x, pb.y);
    }
}

// =============================================================================
// Merged QKV projection GEMM (NT): grid.z selects {input, weight, bias, out, phi}.
// CTA 128x128, 256 threads, 3 stages -> 2 CTAs/SM. PDL consumer.
// =============================================================================
__global__ __launch_bounds__(GTHREADS, 2)
void gemm_qkv(const __half* __restrict__ Xb, const __half* __restrict__ Wb,
              const float* __restrict__ bq, const float* __restrict__ bk,
              const float* __restrict__ bv,
              __half* __restrict__ Qb, __half* __restrict__ Kb,
              __half* __restrict__ Vb) {
    extern __shared__ char sm[];
    const uint32_t sbase = smem_u32(sm);
    const int tid = threadIdx.x;
    const int lane = tid & 31;
    const int wid = tid >> 5;
    const int wm = wid & 3;
    const int wn = wid >> 2;
    const int bm = blockIdx.y;
    const int bn = blockIdx.x;
    const int zi = blockIdx.z;

    const __half* Ab = Xb + (size_t)zi * ASTRIDE;
    const __half* Bb = Wb + (size_t)zi * WSZC;
    const float* bias = (zi == 0) ? bq : (zi == 1) ? bk : bv;
    __half* Yh = (zi == 0) ? Qb : (zi == 1) ? Kb : Vb;
    const bool phi = (zi != 2);

    if (tid == 0) {
        #pragma unroll
        for (int s = 0; s < STAGES; s++) mbar_init(sbase + s * 8, 1);
    }
    __syncthreads();

    const char* gAb = (const char*)Ab + ((size_t)(bm * NCH) << 14);
    const char* gBb = (const char*)Bb + ((size_t)(bn * NCH) << 14);

    int row_a[2];
    row_a[0] = wm * 32 + (lane & 15);
    row_a[1] = row_a[0] + 16;
    const uint32_t a_colb = (uint32_t)((lane >> 4) << 4);
    uint32_t a_base[2], a_mask[2];
    #pragma unroll
    for (int mt = 0; mt < 2; mt++) {
        a_base[mt] = (uint32_t)(row_a[mt] * 128);
        a_mask[mt] = (uint32_t)((row_a[mt] & 7) << 4);
    }
    int nrow[4];
    #pragma unroll
    for (int ntp = 0; ntp < 4; ntp++)
        nrow[ntp] = wn * 64 + ntp * 16 + (lane & 7) + ((lane >> 4) << 3);
    const uint32_t b_colb = (lane & 8) ? 16u : 0u;
    uint32_t b_base[4], b_mask[4];
    #pragma unroll
    for (int ntp = 0; ntp < 4; ntp++) {
        b_base[ntp] = (uint32_t)(nrow[ntp] * 128);
        b_mask[ntp] = (uint32_t)((nrow[ntp] & 7) << 4);
    }

    float acc[2][8][4];
    #pragma unroll
    for (int mt = 0; mt < 2; mt++)
        #pragma unroll
        for (int nt = 0; nt < 8; nt++)
            #pragma unroll
            for (int i = 0; i < 4; i++) acc[mt][nt][i] = 0.f;

    auto issue = [&](int c) {
        const int s = c % STAGES;
        const uint32_t mb = sbase + s * 8;
        const uint32_t st = sbase + 1024 + s * STAGE;
        mbar_expect_tx(mb, 2 * BLK_BYTES);
        bulk_cp(st + A_PL, gAb + ((size_t)c << 14), BLK_BYTES, mb);
        bulk_cp(st + B_PL, gBb + ((size_t)c << 14), BLK_BYTES, mb);
    };

    // wait for cvt_all output before first read (PDL)
    cudaGridDependencySynchronize();

    if (tid == 0) { issue(0); issue(1); }

    for (int c = 0; c < NCH; c++) {
        mbar_wait(sbase + (c % STAGES) * 8, (c / STAGES) & 1);
        if (tid == 0 && c + 2 < NCH) issue(c + 2);

        const uint32_t stg = sbase + 1024 + (uint32_t)((c % STAGES) * STAGE);
        #pragma unroll
        for (int ks = 0; ks < 4; ks++) {
            const uint32_t kb = (uint32_t)(ks * 32);
            uint32_t Ar[2][4];
            #pragma unroll
            for (int mt = 0; mt < 2; mt++) {
                uint32_t off = a_base[mt] + ((kb + a_colb) ^ a_mask[mt]);
                ldsm4(Ar[mt][0], Ar[mt][1], Ar[mt][2], Ar[mt][3], stg + A_PL + off);
            }
            uint32_t Br[8][2];
            #pragma unroll
            for (int ntp = 0; ntp < 4; ntp++) {
                uint32_t off = b_base[ntp] + ((kb + b_colb) ^ b_mask[ntp]);
                ldsm4(Br[2 * ntp][0], Br[2 * ntp][1], Br[2 * ntp + 1][0], Br[2 * ntp + 1][1],
                      stg + B_PL + off);
            }
            #pragma unroll
            for (int mt = 0; mt < 2; mt++)
                #pragma unroll
                for (int nt = 0; nt < 8; nt++)
                    mma_fp16(acc[mt][nt], Ar[mt], Br[nt]);
        }
        __syncthreads();
    }

    // ---- epilogue: bias (+ phi), store fp16 blocked ----
    const int lr = lane >> 2;
    const int lc = lane & 3;
    #pragma unroll
    for (int mt = 0; mt < 2; mt++) {
        const int r0l = wm * 32 + mt * 16 + lr;
        #pragma unroll
        for (int nt = 0; nt < 8; nt++) {
            const int gc = bn * BN + wn * 64 + nt * 8 + lc * 2;
            const float b0 = __ldg(&bias[gc]);
            const float b1 = __ldg(&bias[gc + 1]);
            float o00 = acc[mt][nt][0] + b0;
            float o01 = acc[mt][nt][1] + b1;
            float o10 = acc[mt][nt][2] + b0;
            float o11 = acc[mt][nt][3] + b1;
            if (phi) {
                o00 = (o00 > 0.f) ? (o00 + 1.f) : __expf(o00);
                o01 = (o01 > 0.f) ? (o01 + 1.f) : __expf(o01);
                o10 = (o10 > 0.f) ? (o10 + 1.f) : __expf(o10);
                o11 = (o11 > 0.f) ? (o11 + 1.f) : __expf(o11);
            }
            const int cch = gc >> 6;
            const uint32_t colb = (uint32_t)((gc & 63) * 2);
            const size_t blkb = ((size_t)(bm * NCH + cch)) << 14;
            __half2 p0 = __floats2half2_rn(o00, o01);
            __half2 p1 = __floats2half2_rn(o10, o11);
            const uint32_t ra = (uint32_t)r0l, rb = (uint32_t)(r0l + 8);
            *(uint32_t*)((char*)Yh + blkb + ra * 128 + (colb ^ ((ra & 7) << 4))) =
                *(uint32_t*)&p0;
            *(uint32_t*)((char*)Yh + blkb + rb * 128 + (colb ^ ((rb & 7) << 4))) =
                *(uint32_t*)&p1;
        }
    }
}

// =============================================================================
// Output projection GEMM (fp32 row-major out), same engine. PDL consumer.
// =============================================================================
__global__ __launch_bounds__(GTHREADS, 2)
void gemm_out(const __half* __restrict__ Ab, const __half* __restrict__ Bb,
              const float* __restrict__ bias, float* __restrict__ Y) {
    extern __shared__ char sm[];
    const uint32_t sbase = smem_u32(sm);
    const int tid = threadIdx.x;
    const int lane = tid & 31;
    const int wid = tid >> 5;
    const int wm = wid & 3;
    const int wn = wid >> 2;
    const int bm = blockIdx.y;
    const int bn = blockIdx.x;

    if (tid == 0) {
        #pragma unroll
        for (int s = 0; s < STAGES; s++) mbar_init(sbase + s * 8, 1);
    }
    __syncthreads();

    const char* gAb = (const char*)Ab + ((size_t)(bm * NCH) << 14);
    const char* gBb = (const char*)Bb + ((size_t)(bn * NCH) << 14);

    int row_a[2];
    row_a[0] = wm * 32 + (lane & 15);
    row_a[1] = row_a[0] + 16;
    const uint32_t a_colb = (uint32_t)((lane >> 4) << 4);
    uint32_t a_base[2], a_mask[2];
    #pragma unroll
    for (int mt = 0; mt < 2; mt++) {
        a_base[mt] = (uint32_t)(row_a[mt] * 128);
        a_mask[mt] = (uint32_t)((row_a[mt] & 7) << 4);
    }
    int nrow[4];
    #pragma unroll
    for (int ntp = 0; ntp < 4; ntp++)
        nrow[ntp] = wn * 64 + ntp * 16 + (lane & 7) + ((lane >> 4) << 3);
    const uint32_t b_colb = (lane & 8) ? 16u : 0u;
    uint32_t b_base[4], b_mask[4];
    #pragma unroll
    for (int ntp = 0; ntp < 4; ntp++) {
        b_base[ntp] = (uint32_t)(nrow[ntp] * 128);
        b_mask[ntp] = (uint32_t)((nrow[ntp] & 7) << 4);
    }

    float acc[2][8][4];
    #pragma unroll
    for (int mt = 0; mt < 2; mt++)
        #pragma unroll
        for (int nt = 0; nt < 8; nt++)
            #pragma unroll
            for (int i = 0; i < 4; i++) acc[mt][nt][i] = 0.f;

    auto issue = [&](int c) {
        const int s = c % STAGES;
        const uint32_t mb = sbase + s * 8;
        const uint32_t st = sbase + 1024 + s * STAGE;
        mbar_expect_tx(mb, 2 * BLK_BYTES);
        bulk_cp(st + A_PL, gAb + ((size_t)c << 14), BLK_BYTES, mb);
        bulk_cp(st + B_PL, gBb + ((size_t)c << 14), BLK_BYTES, mb);
    };

    cudaGridDependencySynchronize();

    if (tid == 0) { issue(0); issue(1); }

    for (int c = 0; c < NCH; c++) {
        mbar_wait(sbase + (c % STAGES) * 8, (c / STAGES) & 1);
        if (tid == 0 && c + 2 < NCH) issue(c + 2);

        const uint32_t stg = sbase + 1024 + (uint32_t)((c % STAGES) * STAGE);
        #pragma unroll
        for (int ks = 0; ks < 4; ks++) {
            const uint32_t kb = (uint32_t)(ks * 32);
            uint32_t Ar[2][4];
            #pragma unroll
            for (int mt = 0; mt < 2; mt++) {
                uint32_t off = a_base[mt] + ((kb + a_colb) ^ a_mask[mt]);
                ldsm4(Ar[mt][0], Ar[mt][1], Ar[mt][2], Ar[mt][3], stg + A_PL + off);
            }
            uint32_t Br[8][2];
            #pragma unroll
            for (int ntp = 0; ntp < 4; ntp++) {
                uint32_t off = b_base[ntp] + ((kb + b_colb) ^ b_mask[ntp]);
                ldsm4(Br[2 * ntp][0], Br[2 * ntp][1], Br[2 * ntp + 1][0], Br[2 * ntp + 1][1],
                      stg + B_PL + off);
            }
            #pragma unroll
            for (int mt = 0; mt < 2; mt++)
                #pragma unroll
                for (int nt = 0; nt < 8; nt++)
                    mma_fp16(acc[mt][nt], Ar[mt], Br[nt]);
        }
        __syncthreads();
    }

    const int lr = lane >> 2;
    const int lc = lane & 3;
    #pragma unroll
    for (int mt = 0; mt < 2; mt++) {
        const int gr0 = bm * BM + wm * 32 + mt * 16 + lr;
        #pragma unroll
        for (int nt = 0; nt < 8; nt++) {
            const int gc = bn * BN + wn * 64 + nt * 8 + lc * 2;
            const float b0 = __ldg(&bias[gc]);
            const float b1 = __ldg(&bias[gc + 1]);
            *(float2*)(Y + (size_t)gr0 * DMODEL + gc) =
                make_float2(acc[mt][nt][0] + b0, acc[mt][nt][1] + b1);
            *(float2*)(Y + (size_t)(gr0 + 8) * DMODEL + gc) =
                make_float2(acc[mt][nt][2] + b0, acc[mt][nt][3] + b1);
        }
    }
}

// =============================================================================
// kv partial via HMMA, 256 threads / 8 warps (e-split), KSPLIT=8. PDL consumer.
// =============================================================================
__global__ __launch_bounds__(256, 1)
void kv_hmma(const __half* __restrict__ Kb, const __half* __restrict__ Vb,
             float* __restrict__ kvp, float* __restrict__ zp) {
    extern __shared__ char sm[];
    const uint32_t sbase = smem_u32(sm);
    const int tid = threadIdx.x;
    const int lane = tid & 31;
    const int wid = tid >> 5;

    const int s  = blockIdx.x % KSPLIT;
    const int bh = blockIdx.x / KSPLIT;
    const int b = bh / HEADS, h = bh % HEADS;
    const int blkbase = b * (SEQ / 128) + s * 4;

    if (tid == 0) { mbar_init(sbase, 1); mbar_init(sbase + 8, 1); }
    __syncthreads();

    auto issue = [&](int j) {
        const int st = j & 1;
        const uint32_t mb = sbase + st * 8;
        const uint32_t dst = sbase + 1024 + st * KV_STAGE;
        mbar_expect_tx(mb, 2 * BLK_BYTES);
        const size_t off = ((size_t)((blkbase + j) * NCH + h)) << 14;
        bulk_cp(dst,         (const char*)Kb + off, BLK_BYTES, mb);
        bulk_cp(dst + 16384, (const char*)Vb + off, BLK_BYTES, mb);
    };

    cudaGridDependencySynchronize();
    if (tid == 0) { issue(0); issue(1); }

    const int d0 = (wid & 3) * 16;
    const int eh = wid >> 2;
    const int a_rloc = (lane & 7) + ((lane >> 4) << 3);
    const uint32_t a_cb = (uint32_t)(d0 * 2) + (uint32_t)(((lane >> 3) & 1) << 4);
    const uint32_t a_off = (uint32_t)(a_rloc * 128) + (a_cb ^ ((uint32_t)(a_rloc & 7) << 4));
    const int b_rloc = (lane & 7) + (((lane >> 3) & 1) << 3);
    const uint32_t b_cb0 = (uint32_t)((lane >> 4) << 4);
    uint32_t b_off[2];
    #pragma unroll
    for (int e4 = 0; e4 < 2; e4++)
        b_off[e4] = (uint32_t)(b_rloc * 128)
                  + (((uint32_t)((eh * 2 + e4) * 32) + b_cb0) ^ ((uint32_t)(b_rloc & 7) << 4));

    float acc[4][4];
    #pragma unroll
    for (int nt = 0; nt < 4; nt++)
        #pragma unroll
        for (int i = 0; i < 4; i++) acc[nt][i] = 0.f;
    float zs0 = 0.f, zs1 = 0.f;

    for (int j = 0; j < 4; j++) {
        mbar_wait(sbase + (j & 1) * 8, (j >> 1) & 1);
        const uint32_t bK = sbase + 1024 + (j & 1) * KV_STAGE;
        const uint32_t bV = bK + 16384;
        #pragma unroll
        for (int ks = 0; ks < 8; ks++) {
            uint32_t Ar[4];
            ldsm4t(Ar[0], Ar[1], Ar[2], Ar[3], bK + (uint32_t)(ks * 2048) + a_off);
            uint32_t Br[4][2];
            #pragma unroll
            for (int e4 = 0; e4 < 2; e4++) {
                uint32_t r0, r1, r2, r3;
                ldsm4t(r0, r1, r2, r3, bV + (uint32_t)(ks * 2048) + b_off[e4]);
                Br[2 * e4][0] = r0; Br[2 * e4][1] = r1;
                Br[2 * e4 + 1][0] = r2; Br[2 * e4 + 1][1] = r3;
            }
            #pragma unroll
            for (int nt = 0; nt < 4; nt++) mma_fp16(acc[nt], Ar, Br[nt]);
            if (eh == 0) {
                zs0 += h2sum(Ar[0]) + h2sum(Ar[2]);
                zs1 += h2sum(Ar[1]) + h2sum(Ar[3]);
            }
        }
        __syncthreads();
        if (tid == 0 && j + 2 < 4) issue(j + 2);
    }

    const int g = lane >> 2;
    const int ec = 2 * (lane & 3);
    float* kout = kvp + (size_t)blockIdx.x * (DH * DH);
    #pragma unroll
    for (int nt = 0; nt < 4; nt++) {
        const int e = eh * 32 + nt * 8 + ec;
        *(float2*)&kout[(d0 + g) * DH + e]     = make_float2(acc[nt][0], acc[nt][1]);
        *(float2*)&kout[(d0 + g + 8) * DH + e] = make_float2(acc[nt][2], acc[nt][3]);
    }
    if (eh == 0) {
        zs0 += __shfl_xor_sync(0xFFFFFFFF, zs0, 1);
        zs0 += __shfl_xor_sync(0xFFFFFFFF, zs0, 2);
        zs1 += __shfl_xor_sync(0xFFFFFFFF, zs1, 1);
        zs1 += __shfl_xor_sync(0xFFFFFFFF, zs1, 2);
        if ((lane & 3) == 0) {
            zp[(size_t)blockIdx.x * DH + d0 + g]     = zs0;
            zp[(size_t)blockIdx.x * DH + d0 + g + 8] = zs1;
        }
    }
}

// =============================================================================
// reduce partials -> kvT fp16 swizzled [e][d] + z fp32. PDL consumer.
// =============================================================================
__global__ __launch_bounds__(256)
void kv_reduce(const float* __restrict__ kvp, const float* __restrict__ zp,
               __half* __restrict__ kvT, float* __restrict__ zo) {
    const int bh = blockIdx.x;
    const int tid = threadIdx.x;
    cudaGridDependencySynchronize();
    for (int i = tid; i < DH * DH; i += 256) {
        float sum = 0.f;
        #pragma unroll
        for (int s = 0; s < KSPLIT; s++)
            sum += kvp[((size_t)bh * KSPLIT + s) * (DH * DH) + i];
        const int d = i >> 6, e = i & 63;
        const size_t off = (size_t)bh * 8192 + (uint32_t)(e * 128)
                         + (((uint32_t)(d * 2)) ^ ((uint32_t)(e & 7) << 4));
        *(__half*)((char*)kvT + off) = __float2half_rn(sum);
    }
    if (tid < DH) {
        float sum = 0.f;
        #pragma unroll
        for (int s = 0; s < KSPLIT; s++)
            sum += zp[((size_t)bh * KSPLIT + s) * DH + tid];
        zo[(size_t)bh * DH + tid] = sum;
    }
}

// =============================================================================
// attn via HMMA: out[n][e] = (sum_d Q[n][d] kvT[e][d]) / (q.z + eps).
// grid = (ROWS/128, 2); occupancy 2. PDL consumer.
// =============================================================================
__global__ __launch_bounds__(256, 2)
void attn_hmma(const __half* __restrict__ Qb, const __half* __restrict__ kvT,
               const float* __restrict__ z, __half* __restrict__ Sb) {
    extern __shared__ char sm[];
    __shared__ float zsm[2][64];
    const uint32_t sbase = smem_u32(sm);
    const int tid = threadIdx.x;
    const int lane = tid & 31;
    const int wid = tid >> 5;
    const int blk = blockIdx.x;
    const int h0 = blockIdx.y * 8;
    const int b = blk >> 5;

    if (tid == 0) { mbar_init(sbase, 1); mbar_init(sbase + 8, 1); }

    auto issue = [&](int hh) {
        const int h = h0 + hh;
        const int st = hh & 1;
        const uint32_t mb = sbase + st * 8;
        const uint32_t dst = sbase + 1024 + st * AT_STAGE;
        mbar_expect_tx(mb, 16384 + 8192);
        bulk_cp(dst, (const char*)Qb + (((size_t)(blk * NCH + h)) << 14), 16384, mb);
        bulk_cp(dst + 16384, (const char*)kvT + (((size_t)(b * HEADS + h)) << 13), 8192, mb);
    };
    __syncthreads();
    cudaGridDependencySynchronize();
    if (tid == 0) { issue(0); issue(1); }
    if (tid < 64) {
        zsm[0][tid] = z[(size_t)(b * HEADS + h0 + 0) * DH + tid];
        zsm[1][tid] = z[(size_t)(b * HEADS + h0 + 1) * DH + tid];
    }
    __syncthreads();

    const int row_a = wid * 16 + (lane & 15);
    const uint32_t a_base = (uint32_t)(row_a * 128);
    const uint32_t a_mask = (uint32_t)((row_a & 7) << 4);
    const uint32_t a_colb = (uint32_t)((lane >> 4) << 4);
    int nrow[4];
    #pragma unroll
    for (int ntp = 0; ntp < 4; ntp++)
        nrow[ntp] = ntp * 16 + (lane & 7) + ((lane >> 4) << 3);
    const uint32_t b_colb = (lane & 8) ? 16u : 0u;
    uint32_t b_base[4], b_mask[4];
    #pragma unroll
    for (int ntp = 0; ntp < 4; ntp++) {
        b_base[ntp] = (uint32_t)(nrow[ntp] * 128);
        b_mask[ntp] = (uint32_t)((nrow[ntp] & 7) << 4);
    }

    const int g = lane >> 2;
    const int ec = 2 * (lane & 3);

    for (int hh = 0; hh < 8; hh++) {
        const int h = h0 + hh;
        const int st = hh & 1;
        mbar_wait(sbase + st * 8, (hh >> 1) & 1);
        const uint32_t bQ = sbase + 1024 + st * AT_STAGE;
        const uint32_t bKV = bQ + 16384;

        float acc[8][4];
        #pragma unroll
        for (int nt = 0; nt < 8; nt++)
            #pragma unroll
            for (int i = 0; i < 4; i++) acc[nt][i] = 0.f;
        float den0 = 0.f, den1 = 0.f;

        #pragma unroll
        for (int ks = 0; ks < 4; ks++) {
            const uint32_t kb = (uint32_t)(ks * 32);
            uint32_t Ar[4];
            ldsm4(Ar[0], Ar[1], Ar[2], Ar[3], bQ + a_base + ((kb + a_colb) ^ a_mask));
            uint32_t Br[8][2];
            #pragma unroll
            for (int ntp = 0; ntp < 4; ntp++) {
                uint32_t off = b_base[ntp] + ((kb + b_colb) ^ b_mask[ntp]);
                ldsm4(Br[2 * ntp][0], Br[2 * ntp][1], Br[2 * ntp + 1][0], Br[2 * ntp + 1][1],
                      bKV + off);
            }
            #pragma unroll
            for (int nt = 0; nt < 8; nt++) mma_fp16(acc[nt], Ar, Br[nt]);

            const int dbase = ks * 16 + ec;
            const float z0 = zsm[st][dbase],     z1 = zsm[st][dbase + 1];
            const float z8 = zsm[st][dbase + 8], z9 = zsm[st][dbase + 9];
            float2 a0 = __half22float2(*(__half2*)&Ar[0]);
            float2 a1 = __half22float2(*(__half2*)&Ar[1]);
            float2 a2 = __half22float2(*(__half2*)&Ar[2]);
            float2 a3 = __half22float2(*(__half2*)&Ar[3]);
            den0 += a0.x * z0 + a0.y * z1 + a2.x * z8 + a2.y * z9;
            den1 += a1.x * z0 + a1.y * z1 + a3.x * z8 + a3.y * z9;
        }
        den0 += __shfl_xor_sync(0xFFFFFFFF, den0, 1);
        den0 += __shfl_xor_sync(0xFFFFFFFF, den0, 2);
        den1 += __shfl_xor_sync(0xFFFFFFFF, den1, 1);
        den1 += __shfl_xor_sync(0xFFFFFFFF, den1, 2);
        const float rinv0 = 1.0f / (den0 + EPSV);
        const float rinv1 = 1.0f / (den1 + EPSV);

        const size_t blkb = ((size_t)(blk * NCH + h)) << 14;
        const uint32_t ra = (uint32_t)(wid * 16 + g);
        const uint32_t rb = ra + 8;
        #pragma unroll
        for (int nt = 0; nt < 8; nt++) {
            const uint32_t colb = (uint32_t)((nt * 8 + ec) * 2);
            __half2 p0 = __floats2half2_rn(acc[nt][0] * rinv0, acc[nt][1] * rinv0);
            __half2 p1 = __floats2half2_rn(acc[nt][2] * rinv1, acc[nt][3] * rinv1);
            *(uint32_t*)((char*)Sb + blkb + ra * 128 + (colb ^ ((ra & 7) << 4))) =
                *(uint32_t*)&p0;
            *(uint32_t*)((char*)Sb + blkb + rb * 128 + (colb ^ ((rb & 7) << 4))) =
                *(uint32_t*)&p1;
        }
        __syncthreads();
        if (tid == 0 && hh + 2 < 8) issue(hh + 2);
        if (tid < 64 && hh + 2 < 8)
            zsm[st][tid] = z[(size_t)(b * HEADS + h0 + hh + 2) * DH + tid];
    }
}

// ====================== host-side PDL launch helper =========================
template<typename... Args>
static void launch_pdl(void (*kern)(Args...), dim3 grid, dim3 block, size_t smem,
                       Args... args) {
    cudaLaunchConfig_t cfg = {};
    cfg.gridDim = grid;
    cfg.blockDim = block;
    cfg.dynamicSmemBytes = smem;
    cudaLaunchAttribute attr[1];
    attr[0].id = cudaLaunchAttributeProgrammaticStreamSerialization;
    attr[0].val.programmaticStreamSerializationAllowed = 1;
    cfg.attrs = attr;
    cfg.numAttrs = 1;
    cudaLaunchKernelEx(&cfg, kern, args...);
}

// =============================================================================
extern "C" void kernel_launch(void* const* d_in, const int* in_sizes, int n_in,
                              void* d_out, int out_size) {
    const float* queries = (const float*)d_in[0];
    const float* keys    = (const float*)d_in[1];
    const float* values  = (const float*)d_in[2];
    const float* wq = (const float*)d_in[3];
    const float* bq = (const float*)d_in[4];
    const float* wk = (const float*)d_in[5];
    const float* bk = (const float*)d_in[6];
    const float* wv = (const float*)d_in[7];
    const float* bv = (const float*)d_in[8];
    const float* wo = (const float*)d_in[9];
    const float* bo = (const float*)d_in[10];
    float* out = (float*)d_out;

    __half *Xbp, *Abp, *Wbp, *Qbp, *Kbp, *Vbp, *kvTp;
    float *kvp, *zp, *zb;
    cudaGetSymbolAddress((void**)&Xbp, g_Xb);
    cudaGetSymbolAddress((void**)&Abp, g_Ab);
    cudaGetSymbolAddress((void**)&Wbp, g_Wb);
    cudaGetSymbolAddress((void**)&Qbp, g_Qb);
    cudaGetSymbolAddress((void**)&Kbp, g_Kb);
    cudaGetSymbolAddress((void**)&Vbp, g_Vb);
    cudaGetSymbolAddress((void**)&kvTp, g_kvT);
    cudaGetSymbolAddress((void**)&kvp, g_kvp);
    cudaGetSymbolAddress((void**)&zp,  g_zp);
    cudaGetSymbolAddress((void**)&zb,  g_z);

    cudaFuncSetAttribute(gemm_qkv, cudaFuncAttributeMaxDynamicSharedMemorySize, SMEM_BYTES);
    cudaFuncSetAttribute(gemm_out, cudaFuncAttributeMaxDynamicSharedMemorySize, SMEM_BYTES);
    cudaFuncSetAttribute(kv_hmma,   cudaFuncAttributeMaxDynamicSharedMemorySize, KV_SMEM);
    cudaFuncSetAttribute(attn_hmma, cudaFuncAttributeMaxDynamicSharedMemorySize, AT_SMEM);

    const int XN8 = ROWS * DMODEL / 8;
    const int WN8 = WSZC / 8;

    // one merged conversion launch (z: 4 weights + 3 activations)
    cvt_all<<<dim3(3072, 1, 7), 256>>>(wq, wk, wv, wo, queries, keys, values,
                                       Wbp, Xbp, WN8, XN8);

    // merged QKV projections (3072 CTAs, wave-packed), PDL on cvt
    launch_pdl(gemm_qkv, dim3(DMODEL / BN, ROWS / BM, 3), dim3(GTHREADS), (size_t)SMEM_BYTES,
               (const __half*)Xbp, (const __half*)Wbp, bq, bk, bv, Qbp, Kbp, Vbp);

    launch_pdl(kv_hmma, dim3(BATCH * HEADS * KSPLIT), dim3(256), (size_t)KV_SMEM,
               (const __half*)Kbp, (const __half*)Vbp, kvp, zp);
    launch_pdl(kv_reduce, dim3(BATCH * HEADS), dim3(256), (size_t)0,
               (const float*)kvp, (const float*)zp, kvTp, zb);
    launch_pdl(attn_hmma, dim3(ROWS / 128, 2), dim3(256), (size_t)AT_SMEM,
               (const __half*)Qbp, (const __half*)kvTp, (const float*)zb, Abp);

    // output projection (fp32 out), PDL on attn
    launch_pdl(gemm_out, dim3(DMODEL / BN, ROWS / BM), dim3(GTHREADS), (size_t)SMEM_BYTES,
               (const __half*)Abp, (const __half*)(Wbp + 3 * WSZC), bo, out);
}

// round 16
// speedup vs baseline: 1.1912x; 1.0144x over previous
#include <cuda_runtime.h>
#include <cuda_fp16.h>
#include <cstdint>

// Problem constants (fixed by reference)
#define DMODEL 1024
#define HEADS  16
#define DH     64
#define BATCH  4
#define SEQ    4096
#define ROWS   (BATCH * SEQ)   // 16384
#define KSPLIT 8
#define EPSV   1e-6f

// GEMM tiling (HMMA mma.sync; tcgen05 unavailable on compute_103 virtual arch)
#define BM 128
#define BN 128
#define NCH (DMODEL / 64)       // 16 chunks of 64 fp16 per 1024-row
#define GTHREADS 256
#define STAGES 3                // 99KB smem -> 2 CTAs/SM

// Blocked-swizzled fp16 layout: 16KB block per (row-tile of 128, 64-col chunk).
#define BLK_BYTES 16384

#define A_PL 0
#define B_PL 16384
#define STAGE 32768
#define SMEM_BYTES (1024 + STAGES * STAGE)   // 99328

#define KV_STAGE 32768                        // K 16KB + V 16KB
#define KV_SMEM  (1024 + 2 * KV_STAGE)        // 66560
#define AT_STAGE 24576                        // Q 16KB + kvT 8KB
#define AT_SMEM  (1024 + 2 * AT_STAGE)        // 50176

#define ASTRIDE ((size_t)ROWS * DMODEL)
#define WSZC    (DMODEL * DMODEL)

// ---------------- scratch (device globals; no allocation allowed) ------------
__device__ __half g_Xb[3 * ROWS * DMODEL];          // blocked q/k/v inputs
__device__ __half g_Ab[ROWS * DMODEL];              // S (blocked)
__device__ __half g_Wb[4 * DMODEL * DMODEL];        // blocked wq,wk,wv,wo
__device__ __half g_Qb[ROWS * DMODEL];              // Q fp16 blocked
__device__ __half g_Kb[ROWS * DMODEL];              // K fp16 blocked
__device__ __half g_Vb[ROWS * DMODEL];              // V fp16 blocked
__device__ float g_kvp[BATCH * HEADS * KSPLIT * DH * DH];
__device__ float g_zp [BATCH * HEADS * KSPLIT * DH];
__device__ __half g_kvT[BATCH * HEADS * DH * DH];   // kv^T fp16 swizzled [e][d]
__device__ float g_z  [BATCH * HEADS * DH];

// =============================== helpers ====================================
__device__ __forceinline__ uint32_t smem_u32(const void* p) {
    uint32_t a;
    asm("{ .reg .u64 t; cvta.to.shared.u64 t, %1; cvt.u32.u64 %0, t; }"
        : "=r"(a) : "l"(p));
    return a;
}
__device__ __forceinline__ void ldsm4(uint32_t& r0, uint32_t& r1, uint32_t& r2,
                                      uint32_t& r3, uint32_t addr) {
    asm volatile("ldmatrix.sync.aligned.m8n8.x4.shared.b16 {%0,%1,%2,%3}, [%4];"
                 : "=r"(r0), "=r"(r1), "=r"(r2), "=r"(r3) : "r"(addr));
}
__device__ __forceinline__ void ldsm4t(uint32_t& r0, uint32_t& r1, uint32_t& r2,
                                       uint32_t& r3, uint32_t addr) {
    asm volatile("ldmatrix.sync.aligned.m8n8.x4.trans.shared.b16 {%0,%1,%2,%3}, [%4];"
                 : "=r"(r0), "=r"(r1), "=r"(r2), "=r"(r3) : "r"(addr));
}
__device__ __forceinline__ void mma_fp16(float* c, const uint32_t* a, const uint32_t* b) {
    asm volatile(
        "mma.sync.aligned.m16n8k16.row.col.f32.f16.f16.f32 "
        "{%0,%1,%2,%3}, {%4,%5,%6,%7}, {%8,%9}, {%0,%1,%2,%3};"
        : "+f"(c[0]), "+f"(c[1]), "+f"(c[2]), "+f"(c[3])
        : "r"(a[0]), "r"(a[1]), "r"(a[2]), "r"(a[3]), "r"(b[0]), "r"(b[1]));
}
__device__ __forceinline__ void mbar_init(uint32_t addr, uint32_t cnt) {
    asm volatile("mbarrier.init.shared.b64 [%0], %1;" :: "r"(addr), "r"(cnt) : "memory");
}
__device__ __forceinline__ void mbar_expect_tx(uint32_t addr, uint32_t bytes) {
    asm volatile("mbarrier.arrive.expect_tx.shared.b64 _, [%0], %1;"
                 :: "r"(addr), "r"(bytes) : "memory");
}
__device__ __forceinline__ void mbar_wait(uint32_t addr, uint32_t parity) {
    asm volatile(
        "{\n\t.reg .pred P;\n"
        "W%=:\n\t"
        "mbarrier.try_wait.parity.acquire.cta.shared::cta.b64 P, [%0], %1, 0x989680;\n\t"
        "@!P bra W%=;\n\t"
        "}"
        :: "r"(addr), "r"(parity) : "memory");
}
__device__ __forceinline__ void bulk_cp(uint32_t sdst, const void* gsrc,
                                        uint32_t bytes, uint32_t mbar) {
    asm volatile(
        "cp.async.bulk.shared::cta.global.mbarrier::complete_tx::bytes [%0], [%1], %2, [%3];"
        :: "r"(sdst), "l"(gsrc), "r"(bytes), "r"(mbar) : "memory");
}
__device__ __forceinline__ uint2 cvt_f16x4(float4 v) {
    __half2 p01 = __floats2half2_rn(v.x, v.y);
    __half2 p23 = __floats2half2_rn(v.z, v.w);
    return make_uint2(*(uint32_t*)&p01, *(uint32_t*)&p23);
}
__device__ __forceinline__ float h2sum(uint32_t r) {
    float2 f = __half22float2(*(__half2*)&r);
    return f.x + f.y;
}

// =============================================================================
// Merged conversion: z = 0..3 -> weights, z = 4..6 -> activations.
// fp32 [rows][1024] -> blocked-swizzled fp16; 8 floats -> one 16B store.
// =============================================================================
__global__ __launch_bounds__(256)
void cvt_all(const float* __restrict__ w0, const float* __restrict__ w1,
             const float* __restrict__ w2, const float* __restrict__ w3,
             const float* __restrict__ a0, const float* __restrict__ a1,
             const float* __restrict__ a2,
             __half* __restrict__ Wb, __half* __restrict__ Xb,
             int wn8, int an8) {
    const int zi = blockIdx.z;
    const float* src;
    __half* d;
    int n8;
    if (zi < 4) {
        src = (zi == 0) ? w0 : (zi == 1) ? w1 : (zi == 2) ? w2 : w3;
        d = Wb + (size_t)zi * WSZC;
        n8 = wn8;
    } else {
        src = (zi == 4) ? a0 : (zi == 5) ? a1 : a2;
        d = Xb + (size_t)(zi - 4) * ASTRIDE;
        n8 = an8;
    }
    for (int i = blockIdx.x * 256 + threadIdx.x; i < n8; i += gridDim.x * 256) {
        const int grow = i >> 7;
        const int gcol = (i & 127) * 8;
        const int blk  = grow >> 7;
        const int r    = grow & 127;
        const int c    = gcol >> 6;
        const uint32_t colb = (uint32_t)((gcol & 63) * 2);
        const size_t off = ((size_t)(blk * NCH + c) << 14)
                         + (uint32_t)(r * 128) + (colb ^ ((uint32_t)(r & 7) << 4));
        float4 va = ((const float4*)src)[2 * i];
        float4 vb = ((const float4*)src)[2 * i + 1];
        uint2 pa = cvt_f16x4(va);
        uint2 pb = cvt_f16x4(vb);
        *(uint4*)((char*)d + off) = make_uint4(pa.x, pa.y, pb.x, pb.y);
    }
}

// =============================================================================
// Merged QKV projection GEMM (NT): grid.z selects {input, weight, bias, out, phi}.
// CTA 128x128, 256 threads, 3 stages -> 2 CTAs/SM. PDL consumer.
// =============================================================================
__global__ __launch_bounds__(GTHREADS, 2)
void gemm_qkv(const __half* __restrict__ Xb, const __half* __restrict__ Wb,
              const float* __restrict__ bq, const float* __restrict__ bk,
              const float* __restrict__ bv,
              __half* __restrict__ Qb, __half* __restrict__ Kb,
              __half* __restrict__ Vb) {
    extern __shared__ char sm[];
    const uint32_t sbase = smem_u32(sm);
    const int tid = threadIdx.x;
    const int lane = tid & 31;
    const int wid = tid >> 5;
    const int wm = wid & 3;
    const int wn = wid >> 2;
    const int bm = blockIdx.y;
    const int bn = blockIdx.x;
    const int zi = blockIdx.z;

    const __half* Ab = Xb + (size_t)zi * ASTRIDE;
    const __half* Bb = Wb + (size_t)zi * WSZC;
    const float* bias = (zi == 0) ? bq : (zi == 1) ? bk : bv;
    __half* Yh = (zi == 0) ? Qb : (zi == 1) ? Kb : Vb;
    const bool phi = (zi != 2);

    if (tid == 0) {
        #pragma unroll
        for (int s = 0; s < STAGES; s++) mbar_init(sbase + s * 8, 1);
    }
    __syncthreads();

    const char* gAb = (const char*)Ab + ((size_t)(bm * NCH) << 14);
    const char* gBb = (const char*)Bb + ((size_t)(bn * NCH) << 14);

    int row_a[2];
    row_a[0] = wm * 32 + (lane & 15);
    row_a[1] = row_a[0] + 16;
    const uint32_t a_colb = (uint32_t)((lane >> 4) << 4);
    uint32_t a_base[2], a_mask[2];
    #pragma unroll
    for (int mt = 0; mt < 2; mt++) {
        a_base[mt] = (uint32_t)(row_a[mt] * 128);
        a_mask[mt] = (uint32_t)((row_a[mt] & 7) << 4);
    }
    int nrow[4];
    #pragma unroll
    for (int ntp = 0; ntp < 4; ntp++)
        nrow[ntp] = wn * 64 + ntp * 16 + (lane & 7) + ((lane >> 4) << 3);
    const uint32_t b_colb = (lane & 8) ? 16u : 0u;
    uint32_t b_base[4], b_mask[4];
    #pragma unroll
    for (int ntp = 0; ntp < 4; ntp++) {
        b_base[ntp] = (uint32_t)(nrow[ntp] * 128);
        b_mask[ntp] = (uint32_t)((nrow[ntp] & 7) << 4);
    }

    float acc[2][8][4];
    #pragma unroll
    for (int mt = 0; mt < 2; mt++)
        #pragma unroll
        for (int nt = 0; nt < 8; nt++)
            #pragma unroll
            for (int i = 0; i < 4; i++) acc[mt][nt][i] = 0.f;

    auto issue = [&](int c) {
        const int s = c % STAGES;
        const uint32_t mb = sbase + s * 8;
        const uint32_t st = sbase + 1024 + s * STAGE;
        mbar_expect_tx(mb, 2 * BLK_BYTES);
        bulk_cp(st + A_PL, gAb + ((size_t)c << 14), BLK_BYTES, mb);
        bulk_cp(st + B_PL, gBb + ((size_t)c << 14), BLK_BYTES, mb);
    };

    cudaGridDependencySynchronize();

    if (tid == 0) { issue(0); issue(1); }

    for (int c = 0; c < NCH; c++) {
        mbar_wait(sbase + (c % STAGES) * 8, (c / STAGES) & 1);
        if (tid == 0 && c + 2 < NCH) issue(c + 2);

        const uint32_t stg = sbase + 1024 + (uint32_t)((c % STAGES) * STAGE);
        #pragma unroll
        for (int ks = 0; ks < 4; ks++) {
            const uint32_t kb = (uint32_t)(ks * 32);
            uint32_t Ar[2][4];
            #pragma unroll
            for (int mt = 0; mt < 2; mt++) {
                uint32_t off = a_base[mt] + ((kb + a_colb) ^ a_mask[mt]);
                ldsm4(Ar[mt][0], Ar[mt][1], Ar[mt][2], Ar[mt][3], stg + A_PL + off);
            }
            uint32_t Br[8][2];
            #pragma unroll
            for (int ntp = 0; ntp < 4; ntp++) {
                uint32_t off = b_base[ntp] + ((kb + b_colb) ^ b_mask[ntp]);
                ldsm4(Br[2 * ntp][0], Br[2 * ntp][1], Br[2 * ntp + 1][0], Br[2 * ntp + 1][1],
                      stg + B_PL + off);
            }
            #pragma unroll
            for (int mt = 0; mt < 2; mt++)
                #pragma unroll
                for (int nt = 0; nt < 8; nt++)
                    mma_fp16(acc[mt][nt], Ar[mt], Br[nt]);
        }
        __syncthreads();
    }

    // ---- epilogue: bias (+ phi), store fp16 blocked ----
    const int lr = lane >> 2;
    const int lc = lane & 3;
    #pragma unroll
    for (int mt = 0; mt < 2; mt++) {
        const int r0l = wm * 32 + mt * 16 + lr;
        #pragma unroll
        for (int nt = 0; nt < 8; nt++) {
            const int gc = bn * BN + wn * 64 + nt * 8 + lc * 2;
            const float b0 = __ldg(&bias[gc]);
            const float b1 = __ldg(&bias[gc + 1]);
            float o00 = acc[mt][nt][0] + b0;
            float o01 = acc[mt][nt][1] + b1;
            float o10 = acc[mt][nt][2] + b0;
            float o11 = acc[mt][nt][3] + b1;
            if (phi) {
                o00 = (o00 > 0.f) ? (o00 + 1.f) : __expf(o00);
                o01 = (o01 > 0.f) ? (o01 + 1.f) : __expf(o01);
                o10 = (o10 > 0.f) ? (o10 + 1.f) : __expf(o10);
                o11 = (o11 > 0.f) ? (o11 + 1.f) : __expf(o11);
            }
            const int cch = gc >> 6;
            const uint32_t colb = (uint32_t)((gc & 63) * 2);
            const size_t blkb = ((size_t)(bm * NCH + cch)) << 14;
            __half2 p0 = __floats2half2_rn(o00, o01);
            __half2 p1 = __floats2half2_rn(o10, o11);
            const uint32_t ra = (uint32_t)r0l, rb = (uint32_t)(r0l + 8);
            *(uint32_t*)((char*)Yh + blkb + ra * 128 + (colb ^ ((ra & 7) << 4))) =
                *(uint32_t*)&p0;
            *(uint32_t*)((char*)Yh + blkb + rb * 128 + (colb ^ ((rb & 7) << 4))) =
                *(uint32_t*)&p1;
        }
    }
}

// =============================================================================
// Output projection GEMM (fp32 row-major out), same engine. PDL consumer.
// =============================================================================
__global__ __launch_bounds__(GTHREADS, 2)
void gemm_out(const __half* __restrict__ Ab, const __half* __restrict__ Bb,
              const float* __restrict__ bias, float* __restrict__ Y) {
    extern __shared__ char sm[];
    const uint32_t sbase = smem_u32(sm);
    const int tid = threadIdx.x;
    const int lane = tid & 31;
    const int wid = tid >> 5;
    const int wm = wid & 3;
    const int wn = wid >> 2;
    const int bm = blockIdx.y;
    const int bn = blockIdx.x;

    if (tid == 0) {
        #pragma unroll
        for (int s = 0; s < STAGES; s++) mbar_init(sbase + s * 8, 1);
    }
    __syncthreads();

    const char* gAb = (const char*)Ab + ((size_t)(bm * NCH) << 14);
    const char* gBb = (const char*)Bb + ((size_t)(bn * NCH) << 14);

    int row_a[2];
    row_a[0] = wm * 32 + (lane & 15);
    row_a[1] = row_a[0] + 16;
    const uint32_t a_colb = (uint32_t)((lane >> 4) << 4);
    uint32_t a_base[2], a_mask[2];
    #pragma unroll
    for (int mt = 0; mt < 2; mt++) {
        a_base[mt] = (uint32_t)(row_a[mt] * 128);
        a_mask[mt] = (uint32_t)((row_a[mt] & 7) << 4);
    }
    int nrow[4];
    #pragma unroll
    for (int ntp = 0; ntp < 4; ntp++)
        nrow[ntp] = wn * 64 + ntp * 16 + (lane & 7) + ((lane >> 4) << 3);
    const uint32_t b_colb = (lane & 8) ? 16u : 0u;
    uint32_t b_base[4], b_mask[4];
    #pragma unroll
    for (int ntp = 0; ntp < 4; ntp++) {
        b_base[ntp] = (uint32_t)(nrow[ntp] * 128);
        b_mask[ntp] = (uint32_t)((nrow[ntp] & 7) << 4);
    }

    float acc[2][8][4];
    #pragma unroll
    for (int mt = 0; mt < 2; mt++)
        #pragma unroll
        for (int nt = 0; nt < 8; nt++)
            #pragma unroll
            for (int i = 0; i < 4; i++) acc[mt][nt][i] = 0.f;

    auto issue = [&](int c) {
        const int s = c % STAGES;
        const uint32_t mb = sbase + s * 8;
        const uint32_t st = sbase + 1024 + s * STAGE;
        mbar_expect_tx(mb, 2 * BLK_BYTES);
        bulk_cp(st + A_PL, gAb + ((size_t)c << 14), BLK_BYTES, mb);
        bulk_cp(st + B_PL, gBb + ((size_t)c << 14), BLK_BYTES, mb);
    };

    cudaGridDependencySynchronize();

    if (tid == 0) { issue(0); issue(1); }

    for (int c = 0; c < NCH; c++) {
        mbar_wait(sbase + (c % STAGES) * 8, (c / STAGES) & 1);
        if (tid == 0 && c + 2 < NCH) issue(c + 2);

        const uint32_t stg = sbase + 1024 + (uint32_t)((c % STAGES) * STAGE);
        #pragma unroll
        for (int ks = 0; ks < 4; ks++) {
            const uint32_t kb = (uint32_t)(ks * 32);
            uint32_t Ar[2][4];
            #pragma unroll
            for (int mt = 0; mt < 2; mt++) {
                uint32_t off = a_base[mt] + ((kb + a_colb) ^ a_mask[mt]);
                ldsm4(Ar[mt][0], Ar[mt][1], Ar[mt][2], Ar[mt][3], stg + A_PL + off);
            }
            uint32_t Br[8][2];
            #pragma unroll
            for (int ntp = 0; ntp < 4; ntp++) {
                uint32_t off = b_base[ntp] + ((kb + b_colb) ^ b_mask[ntp]);
                ldsm4(Br[2 * ntp][0], Br[2 * ntp][1], Br[2 * ntp + 1][0], Br[2 * ntp + 1][1],
                      stg + B_PL + off);
            }
            #pragma unroll
            for (int mt = 0; mt < 2; mt++)
                #pragma unroll
                for (int nt = 0; nt < 8; nt++)
                    mma_fp16(acc[mt][nt], Ar[mt], Br[nt]);
        }
        __syncthreads();
    }

    const int lr = lane >> 2;
    const int lc = lane & 3;
    #pragma unroll
    for (int mt = 0; mt < 2; mt++) {
        const int gr0 = bm * BM + wm * 32 + mt * 16 + lr;
        #pragma unroll
        for (int nt = 0; nt < 8; nt++) {
            const int gc = bn * BN + wn * 64 + nt * 8 + lc * 2;
            const float b0 = __ldg(&bias[gc]);
            const float b1 = __ldg(&bias[gc + 1]);
            *(float2*)(Y + (size_t)gr0 * DMODEL + gc) =
                make_float2(acc[mt][nt][0] + b0, acc[mt][nt][1] + b1);
            *(float2*)(Y + (size_t)(gr0 + 8) * DMODEL + gc) =
                make_float2(acc[mt][nt][2] + b0, acc[mt][nt][3] + b1);
        }
    }
}

// =============================================================================
// kv partial via HMMA, 256 threads / 8 warps (e-split), KSPLIT=8. PDL consumer.
// =============================================================================
__global__ __launch_bounds__(256, 1)
void kv_hmma(const __half* __restrict__ Kb, const __half* __restrict__ Vb,
             float* __restrict__ kvp, float* __restrict__ zp) {
    extern __shared__ char sm[];
    const uint32_t sbase = smem_u32(sm);
    const int tid = threadIdx.x;
    const int lane = tid & 31;
    const int wid = tid >> 5;

    const int s  = blockIdx.x % KSPLIT;
    const int bh = blockIdx.x / KSPLIT;
    const int b = bh / HEADS, h = bh % HEADS;
    const int blkbase = b * (SEQ / 128) + s * 4;

    if (tid == 0) { mbar_init(sbase, 1); mbar_init(sbase + 8, 1); }
    __syncthreads();

    auto issue = [&](int j) {
        const int st = j & 1;
        const uint32_t mb = sbase + st * 8;
        const uint32_t dst = sbase + 1024 + st * KV_STAGE;
        mbar_expect_tx(mb, 2 * BLK_BYTES);
        const size_t off = ((size_t)((blkbase + j) * NCH + h)) << 14;
        bulk_cp(dst,         (const char*)Kb + off, BLK_BYTES, mb);
        bulk_cp(dst + 16384, (const char*)Vb + off, BLK_BYTES, mb);
    };

    cudaGridDependencySynchronize();
    if (tid == 0) { issue(0); issue(1); }

    const int d0 = (wid & 3) * 16;
    const int eh = wid >> 2;
    const int a_rloc = (lane & 7) + ((lane >> 4) << 3);
    const uint32_t a_cb = (uint32_t)(d0 * 2) + (uint32_t)(((lane >> 3) & 1) << 4);
    const uint32_t a_off = (uint32_t)(a_rloc * 128) + (a_cb ^ ((uint32_t)(a_rloc & 7) << 4));
    const int b_rloc = (lane & 7) + (((lane >> 3) & 1) << 3);
    const uint32_t b_cb0 = (uint32_t)((lane >> 4) << 4);
    uint32_t b_off[2];
    #pragma unroll
    for (int e4 = 0; e4 < 2; e4++)
        b_off[e4] = (uint32_t)(b_rloc * 128)
                  + (((uint32_t)((eh * 2 + e4) * 32) + b_cb0) ^ ((uint32_t)(b_rloc & 7) << 4));

    float acc[4][4];
    #pragma unroll
    for (int nt = 0; nt < 4; nt++)
        #pragma unroll
        for (int i = 0; i < 4; i++) acc[nt][i] = 0.f;
    float zs0 = 0.f, zs1 = 0.f;

    for (int j = 0; j < 4; j++) {
        mbar_wait(sbase + (j & 1) * 8, (j >> 1) & 1);
        const uint32_t bK = sbase + 1024 + (j & 1) * KV_STAGE;
        const uint32_t bV = bK + 16384;
        #pragma unroll
        for (int ks = 0; ks < 8; ks++) {
            uint32_t Ar[4];
            ldsm4t(Ar[0], Ar[1], Ar[2], Ar[3], bK + (uint32_t)(ks * 2048) + a_off);
            uint32_t Br[4][2];
            #pragma unroll
            for (int e4 = 0; e4 < 2; e4++) {
                uint32_t r0, r1, r2, r3;
                ldsm4t(r0, r1, r2, r3, bV + (uint32_t)(ks * 2048) + b_off[e4]);
                Br[2 * e4][0] = r0; Br[2 * e4][1] = r1;
                Br[2 * e4 + 1][0] = r2; Br[2 * e4 + 1][1] = r3;
            }
            #pragma unroll
            for (int nt = 0; nt < 4; nt++) mma_fp16(acc[nt], Ar, Br[nt]);
            if (eh == 0) {
                zs0 += h2sum(Ar[0]) + h2sum(Ar[2]);
                zs1 += h2sum(Ar[1]) + h2sum(Ar[3]);
            }
        }
        __syncthreads();
        if (tid == 0 && j + 2 < 4) issue(j + 2);
    }

    const int g = lane >> 2;
    const int ec = 2 * (lane & 3);
    float* kout = kvp + (size_t)blockIdx.x * (DH * DH);
    #pragma unroll
    for (int nt = 0; nt < 4; nt++) {
        const int e = eh * 32 + nt * 8 + ec;
        *(float2*)&kout[(d0 + g) * DH + e]     = make_float2(acc[nt][0], acc[nt][1]);
        *(float2*)&kout[(d0 + g + 8) * DH + e] = make_float2(acc[nt][2], acc[nt][3]);
    }
    if (eh == 0) {
        zs0 += __shfl_xor_sync(0xFFFFFFFF, zs0, 1);
        zs0 += __shfl_xor_sync(0xFFFFFFFF, zs0, 2);
        zs1 += __shfl_xor_sync(0xFFFFFFFF, zs1, 1);
        zs1 += __shfl_xor_sync(0xFFFFFFFF, zs1, 2);
        if ((lane & 3) == 0) {
            zp[(size_t)blockIdx.x * DH + d0 + g]     = zs0;
            zp[(size_t)blockIdx.x * DH + d0 + g + 8] = zs1;
        }
    }
}

// =============================================================================
// reduce partials -> kvT fp16 swizzled [e][d] + z fp32. PDL consumer.
// grid = BATCH*HEADS*4 (4 CTAs per bh, quarter of the 64x64 tile each);
// float4 loads across the 8 splits (MLP = 8).
// =============================================================================
__global__ __launch_bounds__(256)
void kv_reduce(const float* __restrict__ kvp, const float* __restrict__ zp,
               __half* __restrict__ kvT, float* __restrict__ zo) {
    const int blk = blockIdx.x;
    const int bh = blk >> 2;
    const int q4 = blk & 3;
    const int tid = threadIdx.x;
    const int i4 = q4 * 1024 + tid * 4;        // 4 consecutive elements (same d)

    cudaGridDependencySynchronize();

    const float* base = kvp + (size_t)bh * KSPLIT * (DH * DH) + i4;
    float4 v = *(const float4*)(base);
    #pragma unroll
    for (int s = 1; s < KSPLIT; s++) {
        float4 p = *(const float4*)(base + (size_t)s * (DH * DH));
        v.x += p.x; v.y += p.y; v.z += p.z; v.w += p.w;
    }
    const int d = i4 >> 6;
    const int e0 = i4 & 63;
    const float sv[4] = {v.x, v.y, v.z, v.w};
    #pragma unroll
    for (int j = 0; j < 4; j++) {
        const int e = e0 + j;
        const size_t off = (size_t)bh * 8192 + (uint32_t)(e * 128)
                         + (((uint32_t)(d * 2)) ^ ((uint32_t)(e & 7) << 4));
        *(__half*)((char*)kvT + off) = __float2half_rn(sv[j]);
    }

    if (q4 == 0 && tid < DH) {
        float sum = 0.f;
        #pragma unroll
        for (int s = 0; s < KSPLIT; s++)
            sum += zp[((size_t)bh * KSPLIT + s) * DH + tid];
        zo[(size_t)bh * DH + tid] = sum;
    }
}

// =============================================================================
// attn via HMMA: out[n][e] = (sum_d Q[n][d] kvT[e][d]) / (q.z + eps).
// grid = (ROWS/128, 2); occupancy 2. PDL consumer.
// =============================================================================
__global__ __launch_bounds__(256, 2)
void attn_hmma(const __half* __restrict__ Qb, const __half* __restrict__ kvT,
               const float* __restrict__ z, __half* __restrict__ Sb) {
    extern __shared__ char sm[];
    __shared__ float zsm[2][64];
    const uint32_t sbase = smem_u32(sm);
    const int tid = threadIdx.x;
    const int lane = tid & 31;
    const int wid = tid >> 5;
    const int blk = blockIdx.x;
    const int h0 = blockIdx.y * 8;
    const int b = blk >> 5;

    if (tid == 0) { mbar_init(sbase, 1); mbar_init(sbase + 8, 1); }

    auto issue = [&](int hh) {
        const int h = h0 + hh;
        const int st = hh & 1;
        const uint32_t mb = sbase + st * 8;
        const uint32_t dst = sbase + 1024 + st * AT_STAGE;
        mbar_expect_tx(mb, 16384 + 8192);
        bulk_cp(dst, (const char*)Qb + (((size_t)(blk * NCH + h)) << 14), 16384, mb);
        bulk_cp(dst + 16384, (const char*)kvT + (((size_t)(b * HEADS + h)) << 13), 8192, mb);
    };
    __syncthreads();
    cudaGridDependencySynchronize();
    if (tid == 0) { issue(0); issue(1); }
    if (tid < 64) {
        zsm[0][tid] = z[(size_t)(b * HEADS + h0 + 0) * DH + tid];
        zsm[1][tid] = z[(size_t)(b * HEADS + h0 + 1) * DH + tid];
    }
    __syncthreads();

    const int row_a = wid * 16 + (lane & 15);
    const uint32_t a_base = (uint32_t)(row_a * 128);
    const uint32_t a_mask = (uint32_t)((row_a & 7) << 4);
    const uint32_t a_colb = (uint32_t)((lane >> 4) << 4);
    int nrow[4];
    #pragma unroll
    for (int ntp = 0; ntp < 4; ntp++)
        nrow[ntp] = ntp * 16 + (lane & 7) + ((lane >> 4) << 3);
    const uint32_t b_colb = (lane & 8) ? 16u : 0u;
    uint32_t b_base[4], b_mask[4];
    #pragma unroll
    for (int ntp = 0; ntp < 4; ntp++) {
        b_base[ntp] = (uint32_t)(nrow[ntp] * 128);
        b_mask[ntp] = (uint32_t)((nrow[ntp] & 7) << 4);
    }

    const int g = lane >> 2;
    const int ec = 2 * (lane & 3);

    for (int hh = 0; hh < 8; hh++) {
        const int h = h0 + hh;
        const int st = hh & 1;
        mbar_wait(sbase + st * 8, (hh >> 1) & 1);
        const uint32_t bQ = sbase + 1024 + st * AT_STAGE;
        const uint32_t bKV = bQ + 16384;

        float acc[8][4];
        #pragma unroll
        for (int nt = 0; nt < 8; nt++)
            #pragma unroll
            for (int i = 0; i < 4; i++) acc[nt][i] = 0.f;
        float den0 = 0.f, den1 = 0.f;

        #pragma unroll
        for (int ks = 0; ks < 4; ks++) {
            const uint32_t kb = (uint32_t)(ks * 32);
            uint32_t Ar[4];
            ldsm4(Ar[0], Ar[1], Ar[2], Ar[3], bQ + a_base + ((kb + a_colb) ^ a_mask));
            uint32_t Br[8][2];
            #pragma unroll
            for (int ntp = 0; ntp < 4; ntp++) {
                uint32_t off = b_base[ntp] + ((kb + b_colb) ^ b_mask[ntp]);
                ldsm4(Br[2 * ntp][0], Br[2 * ntp][1], Br[2 * ntp + 1][0], Br[2 * ntp + 1][1],
                      bKV + off);
            }
            #pragma unroll
            for (int nt = 0; nt < 8; nt++) mma_fp16(acc[nt], Ar, Br[nt]);

            const int dbase = ks * 16 + ec;
            const float z0 = zsm[st][dbase],     z1 = zsm[st][dbase + 1];
            const float z8 = zsm[st][dbase + 8], z9 = zsm[st][dbase + 9];
            float2 a0 = __half22float2(*(__half2*)&Ar[0]);
            float2 a1 = __half22float2(*(__half2*)&Ar[1]);
            float2 a2 = __half22float2(*(__half2*)&Ar[2]);
            float2 a3 = __half22float2(*(__half2*)&Ar[3]);
            den0 += a0.x * z0 + a0.y * z1 + a2.x * z8 + a2.y * z9;
            den1 += a1.x * z0 + a1.y * z1 + a3.x * z8 + a3.y * z9;
        }
        den0 += __shfl_xor_sync(0xFFFFFFFF, den0, 1);
        den0 += __shfl_xor_sync(0xFFFFFFFF, den0, 2);
        den1 += __shfl_xor_sync(0xFFFFFFFF, den1, 1);
        den1 += __shfl_xor_sync(0xFFFFFFFF, den1, 2);
        const float rinv0 = 1.0f / (den0 + EPSV);
        const float rinv1 = 1.0f / (den1 + EPSV);

        const size_t blkb = ((size_t)(blk * NCH + h)) << 14;
        const uint32_t ra = (uint32_t)(wid * 16 + g);
        const uint32_t rb = ra + 8;
        #pragma unroll
        for (int nt = 0; nt < 8; nt++) {
            const uint32_t colb = (uint32_t)((nt * 8 + ec) * 2);
            __half2 p0 = __floats2half2_rn(acc[nt][0] * rinv0, acc[nt][1] * rinv0);
            __half2 p1 = __floats2half2_rn(acc[nt][2] * rinv1, acc[nt][3] * rinv1);
            *(uint32_t*)((char*)Sb + blkb + ra * 128 + (colb ^ ((ra & 7) << 4))) =
                *(uint32_t*)&p0;
            *(uint32_t*)((char*)Sb + blkb + rb * 128 + (colb ^ ((rb & 7) << 4))) =
                *(uint32_t*)&p1;
        }
        __syncthreads();
        if (tid == 0 && hh + 2 < 8) issue(hh + 2);
        if (tid < 64 && hh + 2 < 8)
            zsm[st][tid] = z[(size_t)(b * HEADS + h0 + hh + 2) * DH + tid];
    }
}

// ====================== host-side PDL launch helper =========================
template<typename... Args>
static void launch_pdl(void (*kern)(Args...), dim3 grid, dim3 block, size_t smem,
                       Args... args) {
    cudaLaunchConfig_t cfg = {};
    cfg.gridDim = grid;
    cfg.blockDim = block;
    cfg.dynamicSmemBytes = smem;
    cudaLaunchAttribute attr[1];
    attr[0].id = cudaLaunchAttributeProgrammaticStreamSerialization;
    attr[0].val.programmaticStreamSerializationAllowed = 1;
    cfg.attrs = attr;
    cfg.numAttrs = 1;
    cudaLaunchKernelEx(&cfg, kern, args...);
}

// =============================================================================
extern "C" void kernel_launch(void* const* d_in, const int* in_sizes, int n_in,
                              void* d_out, int out_size) {
    const float* queries = (const float*)d_in[0];
    const float* keys    = (const float*)d_in[1];
    const float* values  = (const float*)d_in[2];
    const float* wq = (const float*)d_in[3];
    const float* bq = (const float*)d_in[4];
    const float* wk = (const float*)d_in[5];
    const float* bk = (const float*)d_in[6];
    const float* wv = (const float*)d_in[7];
    const float* bv = (const float*)d_in[8];
    const float* wo = (const float*)d_in[9];
    const float* bo = (const float*)d_in[10];
    float* out = (float*)d_out;

    __half *Xbp, *Abp, *Wbp, *Qbp, *Kbp, *Vbp, *kvTp;
    float *kvp, *zp, *zb;
    cudaGetSymbolAddress((void**)&Xbp, g_Xb);
    cudaGetSymbolAddress((void**)&Abp, g_Ab);
    cudaGetSymbolAddress((void**)&Wbp, g_Wb);
    cudaGetSymbolAddress((void**)&Qbp, g_Qb);
    cudaGetSymbolAddress((void**)&Kbp, g_Kb);
    cudaGetSymbolAddress((void**)&Vbp, g_Vb);
    cudaGetSymbolAddress((void**)&kvTp, g_kvT);
    cudaGetSymbolAddress((void**)&kvp, g_kvp);
    cudaGetSymbolAddress((void**)&zp,  g_zp);
    cudaGetSymbolAddress((void**)&zb,  g_z);

    cudaFuncSetAttribute(gemm_qkv, cudaFuncAttributeMaxDynamicSharedMemorySize, SMEM_BYTES);
    cudaFuncSetAttribute(gemm_out, cudaFuncAttributeMaxDynamicSharedMemorySize, SMEM_BYTES);
    cudaFuncSetAttribute(kv_hmma,   cudaFuncAttributeMaxDynamicSharedMemorySize, KV_SMEM);
    cudaFuncSetAttribute(attn_hmma, cudaFuncAttributeMaxDynamicSharedMemorySize, AT_SMEM);

    const int XN8 = ROWS * DMODEL / 8;
    const int WN8 = WSZC / 8;

    // one merged conversion launch (z: 4 weights + 3 activations)
    cvt_all<<<dim3(3072, 1, 7), 256>>>(wq, wk, wv, wo, queries, keys, values,
                                       Wbp, Xbp, WN8, XN8);

    // merged QKV projections (3072 CTAs, wave-packed), PDL on cvt
    launch_pdl(gemm_qkv, dim3(DMODEL / BN, ROWS / BM, 3), dim3(GTHREADS), (size_t)SMEM_BYTES,
               (const __half*)Xbp, (const __half*)Wbp, bq, bk, bv, Qbp, Kbp, Vbp);

    launch_pdl(kv_hmma, dim3(BATCH * HEADS * KSPLIT), dim3(256), (size_t)KV_SMEM,
               (const __half*)Kbp, (const __half*)Vbp, kvp, zp);
    launch_pdl(kv_reduce, dim3(BATCH * HEADS * 4), dim3(256), (size_t)0,
               (const float*)kvp, (const float*)zp, kvTp, zb);
    launch_pdl(attn_hmma, dim3(ROWS / 128, 2), dim3(256), (size_t)AT_SMEM,
               (const __half*)Qbp, (const __half*)kvTp, (const float*)zb, Abp);

    // output projection (fp32 out), PDL on attn
    launch_pdl(gemm_out, dim3(DMODEL / BN, ROWS / BM), dim3(GTHREADS), (size_t)SMEM_BYTES,
               (const __half*)Abp, (const __half*)(Wbp + 3 * WSZC), bo, out);
}